// round 14
// baseline (speedup 1.0000x reference)
#include <cuda_runtime.h>
#include <cstdint>

#define SSCALE 1.6666666666666667f

__device__ __forceinline__ float ssilu(float x) {
    float e = __expf(-x);
    return SSCALE * __fdividef(x, 1.0f + e);
}

// ---- bf16 split + mma helpers ----
__device__ __forceinline__ void split2(float v0, float v1, uint32_t& hi, uint32_t& lo) {
    asm("cvt.rn.bf16x2.f32 %0, %1, %2;" : "=r"(hi) : "f"(v1), "f"(v0));
    float h0 = __uint_as_float(hi << 16);
    float h1 = __uint_as_float(hi & 0xFFFF0000u);
    float r0 = v0 - h0, r1 = v1 - h1;
    asm("cvt.rn.bf16x2.f32 %0, %1, %2;" : "=r"(lo) : "f"(r1), "f"(r0));
}
__device__ __forceinline__ void mma_bf16(float* d, uint32_t a0, uint32_t a1,
                                         uint32_t a2, uint32_t a3,
                                         uint32_t b0, uint32_t b1) {
    asm("mma.sync.aligned.m16n8k16.row.col.f32.bf16.bf16.f32 "
        "{%0,%1,%2,%3}, {%4,%5,%6,%7}, {%8,%9}, {%0,%1,%2,%3};"
        : "+f"(d[0]), "+f"(d[1]), "+f"(d[2]), "+f"(d[3])
        : "r"(a0), "r"(a1), "r"(a2), "r"(a3), "r"(b0), "r"(b1));
}
#define LDSM4(d0, d1, d2, d3, a) asm volatile( \
    "ldmatrix.sync.aligned.m8n8.x4.shared.b16 {%0,%1,%2,%3}, [%4];" \
    : "=r"(d0), "=r"(d1), "=r"(d2), "=r"(d3) : "r"(a))
#define LDSM4T(d0, d1, d2, d3, a) asm volatile( \
    "ldmatrix.sync.aligned.m8n8.x4.trans.shared.b16 {%0,%1,%2,%3}, [%4];" \
    : "=r"(d0), "=r"(d1), "=r"(d2), "=r"(d3) : "r"(a))

__device__ __forceinline__ uint32_t smem_u32(const void* p) {
    uint32_t a;
    asm("{ .reg .u64 t; cvta.to.shared.u64 t, %1; cvt.u32.u64 %0, t; }"
        : "=r"(a) : "l"(p));
    return a;
}

#define E_MAX 700000
#define N_MAX 40000

__device__ __align__(16) float g_xdown[(size_t)E_MAX * 16];
__device__ __align__(16) float g_xe[(size_t)E_MAX * 16];
__device__ __align__(16) float g_h[(size_t)N_MAX * 128];

// ---------------- K0: zero scratch ----------------
__global__ void k_zero(int n_xe4, int n_h4) {
    int i = blockIdx.x * blockDim.x + threadIdx.x;
    int stride = gridDim.x * blockDim.x;
    float4 z = make_float4(0.f, 0.f, 0.f, 0.f);
    for (int r = i; r < n_xe4; r += stride) ((float4*)g_xe)[r] = z;
    for (int r = i; r < n_h4; r += stride) ((float4*)g_h)[r] = z;
}

// ---------------- K1: edge dense + down projection (all HMMA) -------------
#define OFF_BH  0
#define OFF_BL  34816
#define OFF_WRH 69632
#define OFF_WRL 73984
#define OFF_WDH 78336
#define OFF_WDL 82432
#define OFF_AH  86528
#define OFF_AL  103936
#define OFF_RBH 121344
#define OFF_RBL 124416
#define K1_SMEM 127488

__global__ __launch_bounds__(256, 1) void k_edge_down_hmma(
    const float* __restrict__ m, const float* __restrict__ rbf,
    const float* __restrict__ Wba, const float* __restrict__ Wrbf,
    const float* __restrict__ Wdown, int E)
{
    extern __shared__ char smem[];
    uint32_t sb = smem_u32(smem);
    int tid = threadIdx.x;
    int l = tid & 31, w = tid >> 5;

    for (int i = tid; i < 8192; i += 256) {
        int k = i >> 6, n = (i & 63) * 2;
        float v0 = Wba[(size_t)k * 128 + n];
        float v1 = Wba[(size_t)k * 128 + n + 1];
        uint32_t hp, lp;
        split2(v0, v1, hp, lp);
        *(uint32_t*)(smem + OFF_BH + k * 272 + n * 2) = hp;
        *(uint32_t*)(smem + OFF_BL + k * 272 + n * 2) = lp;
    }
    for (int i = tid; i < 1024; i += 256) {
        int k = i >> 6, n = (i & 63) * 2;
        float v0 = Wrbf[(size_t)k * 128 + n];
        float v1 = Wrbf[(size_t)k * 128 + n + 1];
        uint32_t hp, lp;
        split2(v0, v1, hp, lp);
        *(uint32_t*)(smem + OFF_WRH + k * 272 + n * 2) = hp;
        *(uint32_t*)(smem + OFF_WRL + k * 272 + n * 2) = lp;
    }
    for (int i = tid; i < 1024; i += 256) {
        int k = i >> 3, n = (i & 7) * 2;
        float v0 = Wdown[(size_t)k * 16 + n];
        float v1 = Wdown[(size_t)k * 16 + n + 1];
        uint32_t hp, lp;
        split2(v0, v1, hp, lp);
        *(uint32_t*)(smem + OFF_WDH + k * 32 + n * 2) = hp;
        *(uint32_t*)(smem + OFF_WDL + k * 32 + n * 2) = lp;
    }
    __syncthreads();   // weights ready before hoisted fragment loads

    int rowm = (l < 16) ? l : (l - 16);
    int colo = (l < 16) ? 0 : 8;
    int rb = w & 3, ch = w >> 2;
    int r_ = l >> 2, cc2 = (l & 3) * 2;

    uint32_t aH = sb + OFF_AH + (rb * 16 + rowm) * 272 + colo * 2;
    uint32_t aL = aH + (OFF_AL - OFF_AH);
    uint32_t rH = sb + OFF_RBH + (rb * 16 + rowm) * 48 + colo * 2;
    uint32_t rL = rH + (OFF_RBL - OFF_RBH);
    uint32_t bH = sb + OFF_BH + rowm * 272 + (ch * 64 + colo) * 2;
    uint32_t bL = bH + (OFF_BL - OFF_BH);
    uint32_t wrH = sb + OFF_WRH + rowm * 272 + (ch * 64 + colo) * 2;
    uint32_t wrL = wrH + (OFF_WRL - OFF_WRH);
    uint32_t wdH = sb + OFF_WDH + rowm * 32 + colo * 2;
    uint32_t wdL = wdH + (OFF_WDL - OFF_WDH);

    // hoisted W_rbf B fragments (loop-invariant)
    uint32_t wrb[4][8], wrc[4][8];
    #pragma unroll
    for (int p = 0; p < 4; p++) {
        LDSM4T(wrb[p][0], wrb[p][1], wrb[p][2], wrb[p][3], wrH + p * 32);
        LDSM4T(wrc[p][0], wrc[p][1], wrc[p][2], wrc[p][3], wrL + p * 32);
    }

    char* sXH = smem + OFF_AH;
    char* sXL = smem + OFF_AL;

    int ntiles = (E + 63) >> 6;
    for (int tile = blockIdx.x; tile < ntiles; tile += gridDim.x) {
        int e0 = tile << 6;
        __syncthreads();

        #pragma unroll 4
        for (int it = 0; it < 8; it++) {
            int r = tid + it * 256;
            int e = r >> 5, kq = r & 31;
            float4 v = make_float4(0.f, 0.f, 0.f, 0.f);
            if (e0 + e < E) v = *(const float4*)(m + (size_t)(e0 + e) * 128 + kq * 4);
            uint32_t h01, l01, h23, l23;
            split2(v.x, v.y, h01, l01);
            split2(v.z, v.w, h23, l23);
            *(unsigned long long*)(smem + OFF_AH + e * 272 + kq * 8) =
                ((unsigned long long)h23 << 32) | h01;
            *(unsigned long long*)(smem + OFF_AL + e * 272 + kq * 8) =
                ((unsigned long long)l23 << 32) | l01;
        }
        {
            int e = tid >> 2, kp = tid & 3;
            #pragma unroll
            for (int half = 0; half < 2; half++) {
                int k = (kp + half * 4) * 2;
                float2 v = make_float2(0.f, 0.f);
                if (e0 + e < E) v = *(const float2*)(rbf + (size_t)(e0 + e) * 16 + k);
                uint32_t hp, lp;
                split2(v.x, v.y, hp, lp);
                *(uint32_t*)(smem + OFF_RBH + e * 48 + k * 2) = hp;
                *(uint32_t*)(smem + OFF_RBL + e * 48 + k * 2) = lp;
            }
        }
        __syncthreads();

        float rw[8][4];
        #pragma unroll
        for (int t = 0; t < 8; t++) {
            rw[t][0] = 0.f; rw[t][1] = 0.f; rw[t][2] = 0.f; rw[t][3] = 0.f;
        }
        {
            uint32_t ra0, ra1, ra2, ra3, rl0, rl1, rl2, rl3;
            LDSM4(ra0, ra1, ra2, ra3, rH);
            LDSM4(rl0, rl1, rl2, rl3, rL);
            #pragma unroll
            for (int p = 0; p < 4; p++) {
                mma_bf16(rw[p * 2], ra0, ra1, ra2, ra3, wrb[p][0], wrb[p][1]);
                mma_bf16(rw[p * 2], rl0, rl1, rl2, rl3, wrb[p][0], wrb[p][1]);
                mma_bf16(rw[p * 2], ra0, ra1, ra2, ra3, wrc[p][0], wrc[p][1]);
                mma_bf16(rw[p * 2 + 1], ra0, ra1, ra2, ra3, wrb[p][2], wrb[p][3]);
                mma_bf16(rw[p * 2 + 1], rl0, rl1, rl2, rl3, wrb[p][2], wrb[p][3]);
                mma_bf16(rw[p * 2 + 1], ra0, ra1, ra2, ra3, wrc[p][2], wrc[p][3]);
            }
        }

        float acc[8][4];
        #pragma unroll
        for (int t = 0; t < 8; t++) {
            acc[t][0] = 0.f; acc[t][1] = 0.f; acc[t][2] = 0.f; acc[t][3] = 0.f;
        }
        #pragma unroll
        for (int ks = 0; ks < 8; ks++) {
            uint32_t ah0, ah1, ah2, ah3, al0, al1, al2, al3;
            LDSM4(ah0, ah1, ah2, ah3, aH + ks * 32);
            LDSM4(al0, al1, al2, al3, aL + ks * 32);
            uint32_t bkb = bH + ks * 16 * 272;
            uint32_t lkb = bL + ks * 16 * 272;
            #pragma unroll
            for (int p = 0; p < 4; p++) {
                uint32_t b0, b1, b2, b3, c0, c1, c2, c3;
                LDSM4T(b0, b1, b2, b3, bkb + p * 32);
                LDSM4T(c0, c1, c2, c3, lkb + p * 32);
                mma_bf16(acc[p * 2], ah0, ah1, ah2, ah3, b0, b1);
                mma_bf16(acc[p * 2], al0, al1, al2, al3, b0, b1);
                mma_bf16(acc[p * 2], ah0, ah1, ah2, ah3, c0, c1);
                mma_bf16(acc[p * 2 + 1], ah0, ah1, ah2, ah3, b2, b3);
                mma_bf16(acc[p * 2 + 1], al0, al1, al2, al3, b2, b3);
                mma_bf16(acc[p * 2 + 1], ah0, ah1, ah2, ah3, c2, c3);
            }
        }

        __syncthreads();

        {
            int row0 = rb * 16 + r_;
            #pragma unroll
            for (int t = 0; t < 8; t++) {
                int colb = (ch * 64 + t * 8 + cc2) * 2;
                float x0 = ssilu(acc[t][0]) * rw[t][0];
                float x1 = ssilu(acc[t][1]) * rw[t][1];
                float x2 = ssilu(acc[t][2]) * rw[t][2];
                float x3 = ssilu(acc[t][3]) * rw[t][3];
                uint32_t hp, lp;
                split2(x0, x1, hp, lp);
                *(uint32_t*)(sXH + row0 * 272 + colb) = hp;
                *(uint32_t*)(sXL + row0 * 272 + colb) = lp;
                split2(x2, x3, hp, lp);
                *(uint32_t*)(sXH + (row0 + 8) * 272 + colb) = hp;
                *(uint32_t*)(sXL + (row0 + 8) * 272 + colb) = lp;
            }
        }
        __syncthreads();

        // down projection via HMMA on all 8 warps:
        // warp = (row-block rb, n-tile nt = ch): nt covers cols nt*8..nt*8+7
        {
            float d0[4] = {0.f, 0.f, 0.f, 0.f};
            int nt = ch;
            #pragma unroll
            for (int ks = 0; ks < 8; ks++) {
                uint32_t xh0, xh1, xh2, xh3, xl0, xl1, xl2, xl3;
                LDSM4(xh0, xh1, xh2, xh3, aH + ks * 32);
                LDSM4(xl0, xl1, xl2, xl3, aL + ks * 32);
                uint32_t b0, b1, b2, b3, c0, c1, c2, c3;
                LDSM4T(b0, b1, b2, b3, wdH + ks * 512);
                LDSM4T(c0, c1, c2, c3, wdL + ks * 512);
                uint32_t bb0 = nt ? b2 : b0, bb1 = nt ? b3 : b1;
                uint32_t cb0 = nt ? c2 : c0, cb1 = nt ? c3 : c1;
                mma_bf16(d0, xh0, xh1, xh2, xh3, bb0, bb1);
                mma_bf16(d0, xl0, xl1, xl2, xl3, bb0, bb1);
                mma_bf16(d0, xh0, xh1, xh2, xh3, cb0, cb1);
            }
            int e_row = e0 + rb * 16 + r_;
            int colb = nt * 8 + cc2;
            if (e_row < E)
                *(float2*)(g_xdown + (size_t)e_row * 16 + colb) = make_float2(d0[0], d0[1]);
            if (e_row + 8 < E)
                *(float2*)(g_xdown + (size_t)(e_row + 8) * 16 + colb) = make_float2(d0[2], d0[3]);
        }
    }
}

// ---------------- K2: triplet stage via HMMA (pipelined gather) -----------
#define T3_CBH 0
#define T3_CBL 4096
#define T3_WCH 8192
#define T3_WCL 8704
#define T3_XD  9216
#define T3_BA  17408
#define T3_CA  17920
#define T3_SMEM 18432

__global__ __launch_bounds__(256) void k_triplet_hmma(
    const float* __restrict__ cbf,
    const int* __restrict__ ba, const int* __restrict__ ca,
    const float* __restrict__ Wcbf, int T)
{
    __shared__ __align__(16) char smem[T3_SMEM];
    uint32_t sb = smem_u32(smem);
    int tid = threadIdx.x;
    int l = tid & 31, w = tid >> 5;
    int t0 = blockIdx.x << 7;

    int* sBa = (int*)(smem + T3_BA);
    int* sCa = (int*)(smem + T3_CA);
    float* sXd = (float*)(smem + T3_XD);

    if (tid < 128) {
        int k = tid >> 3, n = (tid & 7) * 2;
        float v0 = Wcbf[k * 16 + n], v1 = Wcbf[k * 16 + n + 1];
        uint32_t hp, lp;
        split2(v0, v1, hp, lp);
        *(uint32_t*)(smem + T3_WCH + k * 32 + n * 2) = hp;
        *(uint32_t*)(smem + T3_WCL + k * 32 + n * 2) = lp;
    } else {
        int ti = tid - 128;
        int t = t0 + ti;
        bool ok = t < T;
        sBa[ti] = ok ? ba[t] : 0;
        sCa[ti] = ok ? ca[t] : -1;
    }
    __syncthreads();

    int gr = tid >> 1, ghalf = tid & 1;
    int gb = sBa[gr];
    float4 g0 = *(const float4*)(g_xdown + (size_t)gb * 16 + ghalf * 8);
    float4 g1 = *(const float4*)(g_xdown + (size_t)gb * 16 + ghalf * 8 + 4);

    {
        int e = tid >> 1, q = tid & 1;
        int t = t0 + e;
        bool ok = t < T;
        #pragma unroll
        for (int j = 0; j < 2; j++) {
            int qq = q * 2 + j;
            float4 v = make_float4(0.f, 0.f, 0.f, 0.f);
            if (ok) v = *(const float4*)(cbf + (size_t)t * 16 + qq * 4);
            uint32_t h01, l01, h23, l23;
            split2(v.x, v.y, h01, l01);
            split2(v.z, v.w, h23, l23);
            *(unsigned long long*)(smem + T3_CBH + e * 32 + qq * 8) =
                ((unsigned long long)h23 << 32) | h01;
            *(unsigned long long*)(smem + T3_CBL + e * 32 + qq * 8) =
                ((unsigned long long)l23 << 32) | l01;
        }
    }
    *(float4*)&sXd[gr * 16 + ghalf * 8] = g0;
    *(float4*)&sXd[gr * 16 + ghalf * 8 + 4] = g1;
    __syncthreads();

    int rowm = (l < 16) ? l : (l - 16);
    int colo = (l < 16) ? 0 : 8;
    int r_ = l >> 2, cc = (l & 3) * 2;

    uint32_t aH = sb + T3_CBH + (w * 16 + rowm) * 32 + colo * 2;
    uint32_t aL = aH + (T3_CBL - T3_CBH);
    uint32_t bHa = sb + T3_WCH + rowm * 32 + colo * 2;
    uint32_t bLa = bHa + (T3_WCL - T3_WCH);

    uint32_t ah0, ah1, ah2, ah3, al0, al1, al2, al3;
    uint32_t b0, b1, b2, b3, c0, c1, c2, c3;
    LDSM4(ah0, ah1, ah2, ah3, aH);
    LDSM4(al0, al1, al2, al3, aL);
    LDSM4T(b0, b1, b2, b3, bHa);
    LDSM4T(c0, c1, c2, c3, bLa);

    float u[2][4];
    u[0][0]=u[0][1]=u[0][2]=u[0][3]=0.f;
    u[1][0]=u[1][1]=u[1][2]=u[1][3]=0.f;
    mma_bf16(u[0], ah0, ah1, ah2, ah3, b0, b1);
    mma_bf16(u[0], al0, al1, al2, al3, b0, b1);
    mma_bf16(u[0], ah0, ah1, ah2, ah3, c0, c1);
    mma_bf16(u[1], ah0, ah1, ah2, ah3, b2, b3);
    mma_bf16(u[1], al0, al1, al2, al3, b2, b3);
    mma_bf16(u[1], ah0, ah1, ah2, ah3, c2, c3);

    #pragma unroll
    for (int t = 0; t < 2; t++) {
        int col = t * 8 + cc;
        #pragma unroll
        for (int hh = 0; hh < 2; hh++) {
            int row = w * 16 + r_ + 8 * hh;
            int c_ = sCa[row];
            if (c_ < 0) continue;
            float2 xd = *(float2*)&sXd[row * 16 + col];
            float v0 = u[t][2 * hh] * xd.x;
            float v1 = u[t][2 * hh + 1] * xd.y;
            asm volatile("red.global.add.v2.f32 [%0], {%1,%2};"
                         :: "l"(g_xe + (size_t)c_ * 16 + col),
                            "f"(v0), "f"(v1) : "memory");
        }
    }
}

// ---------------- K3: edge up-projection + atom scatter (HMMA, occ4) ------
#define OFF2_UPH 0
#define OFF2_UPL 4352
#define OFF2_RAH 8704
#define OFF2_RAL 13056
#define OFF2_XEH 17408
#define OFF2_XEL 20480
#define OFF2_RBH 23552
#define OFF2_RBL 26624
#define OFF2_IDX 29696
#define K3_SMEM  29952

__global__ __launch_bounds__(256, 4) void k_edge_up_hmma(
    const float* __restrict__ m, const float* __restrict__ rbf,
    const int* __restrict__ idxt,
    const float* __restrict__ Wup, const float* __restrict__ Wra, int E)
{
    __shared__ __align__(16) char smem[K3_SMEM];
    uint32_t sb = smem_u32(smem);
    int tid = threadIdx.x;
    int l = tid & 31, w = tid >> 5;

    for (int i = tid; i < 1024; i += 256) {
        int k = i >> 6, n = (i & 63) * 2;
        float v0 = Wup[(size_t)k * 128 + n], v1 = Wup[(size_t)k * 128 + n + 1];
        uint32_t hp, lp;
        split2(v0, v1, hp, lp);
        *(uint32_t*)(smem + OFF2_UPH + k * 272 + n * 2) = hp;
        *(uint32_t*)(smem + OFF2_UPL + k * 272 + n * 2) = lp;
        v0 = Wra[(size_t)k * 128 + n]; v1 = Wra[(size_t)k * 128 + n + 1];
        split2(v0, v1, hp, lp);
        *(uint32_t*)(smem + OFF2_RAH + k * 272 + n * 2) = hp;
        *(uint32_t*)(smem + OFF2_RAL + k * 272 + n * 2) = lp;
    }

    int rowm = (l < 16) ? l : (l - 16);
    int colo = (l < 16) ? 0 : 8;
    int rb = w & 3, ch = w >> 2;
    int r_ = l >> 2, cc = (l & 3) * 2;

    uint32_t xH = sb + OFF2_XEH + (rb * 16 + rowm) * 48 + colo * 2;
    uint32_t xL = xH + (OFF2_XEL - OFF2_XEH);
    uint32_t rbH = sb + OFF2_RBH + (rb * 16 + rowm) * 48 + colo * 2;
    uint32_t rbL = rbH + (OFF2_RBL - OFF2_RBH);
    uint32_t bUH = sb + OFF2_UPH + rowm * 272 + (ch * 64 + colo) * 2;
    uint32_t bUL = bUH + (OFF2_UPL - OFF2_UPH);
    uint32_t bRH = sb + OFF2_RAH + rowm * 272 + (ch * 64 + colo) * 2;
    uint32_t bRL = bRH + (OFF2_RAL - OFF2_RAH);
    int* sIdx = (int*)(smem + OFF2_IDX);

    int ntiles = (E + 63) >> 6;
    for (int tile = blockIdx.x; tile < ntiles; tile += gridDim.x) {
        int e0 = tile << 6;
        __syncthreads();

        {
            int e = tid >> 2, q = tid & 3;
            float4 vx = make_float4(0.f, 0.f, 0.f, 0.f), vr = vx;
            if (e0 + e < E) {
                vx = *(const float4*)(g_xe + (size_t)(e0 + e) * 16 + q * 4);
                vr = *(const float4*)(rbf + (size_t)(e0 + e) * 16 + q * 4);
            }
            uint32_t h01, l01, h23, l23;
            split2(vx.x, vx.y, h01, l01); split2(vx.z, vx.w, h23, l23);
            *(unsigned long long*)(smem + OFF2_XEH + e * 48 + q * 8) =
                ((unsigned long long)h23 << 32) | h01;
            *(unsigned long long*)(smem + OFF2_XEL + e * 48 + q * 8) =
                ((unsigned long long)l23 << 32) | l01;
            split2(vr.x, vr.y, h01, l01); split2(vr.z, vr.w, h23, l23);
            *(unsigned long long*)(smem + OFF2_RBH + e * 48 + q * 8) =
                ((unsigned long long)h23 << 32) | h01;
            *(unsigned long long*)(smem + OFF2_RBL + e * 48 + q * 8) =
                ((unsigned long long)l23 << 32) | l01;
        }
        if (tid < 64) sIdx[tid] = (e0 + tid < E) ? idxt[e0 + tid] : -1;
        __syncthreads();

        uint32_t xh0, xh1, xh2, xh3, xl0, xl1, xl2, xl3;
        uint32_t rh0, rh1, rh2, rh3, rl0, rl1, rl2, rl3;
        LDSM4(xh0, xh1, xh2, xh3, xH);
        LDSM4(xl0, xl1, xl2, xl3, xL);
        LDSM4(rh0, rh1, rh2, rh3, rbH);
        LDSM4(rl0, rl1, rl2, rl3, rbL);

        #pragma unroll
        for (int p = 0; p < 4; p++) {
            float u[2][4], rr[2][4];
            u[0][0]=u[0][1]=u[0][2]=u[0][3]=0.f;
            u[1][0]=u[1][1]=u[1][2]=u[1][3]=0.f;
            rr[0][0]=rr[0][1]=rr[0][2]=rr[0][3]=0.f;
            rr[1][0]=rr[1][1]=rr[1][2]=rr[1][3]=0.f;
            {
                uint32_t b0, b1, b2, b3, c0, c1, c2, c3;
                LDSM4T(b0, b1, b2, b3, bUH + p * 32);
                LDSM4T(c0, c1, c2, c3, bUL + p * 32);
                mma_bf16(u[0], xh0, xh1, xh2, xh3, b0, b1);
                mma_bf16(u[0], xl0, xl1, xl2, xl3, b0, b1);
                mma_bf16(u[0], xh0, xh1, xh2, xh3, c0, c1);
                mma_bf16(u[1], xh0, xh1, xh2, xh3, b2, b3);
                mma_bf16(u[1], xl0, xl1, xl2, xl3, b2, b3);
                mma_bf16(u[1], xh0, xh1, xh2, xh3, c2, c3);
            }
            {
                uint32_t b0, b1, b2, b3, c0, c1, c2, c3;
                LDSM4T(b0, b1, b2, b3, bRH + p * 32);
                LDSM4T(c0, c1, c2, c3, bRL + p * 32);
                mma_bf16(rr[0], rh0, rh1, rh2, rh3, b0, b1);
                mma_bf16(rr[0], rl0, rl1, rl2, rl3, b0, b1);
                mma_bf16(rr[0], rh0, rh1, rh2, rh3, c0, c1);
                mma_bf16(rr[1], rh0, rh1, rh2, rh3, b2, b3);
                mma_bf16(rr[1], rl0, rl1, rl2, rl3, b2, b3);
                mma_bf16(rr[1], rh0, rh1, rh2, rh3, c2, c3);
            }
            #pragma unroll
            for (int tt = 0; tt < 2; tt++) {
                int col = ch * 64 + (2 * p + tt) * 8 + cc;
                #pragma unroll
                for (int hh = 0; hh < 2; hh++) {
                    int row = rb * 16 + r_ + 8 * hh;
                    int a = sIdx[row];
                    if (a < 0) continue;
                    float2 mm = *(const float2*)(m + (size_t)(e0 + row) * 128 + col);
                    float h0 = (mm.x + ssilu(u[tt][2 * hh])) * rr[tt][2 * hh];
                    float h1 = (mm.y + ssilu(u[tt][2 * hh + 1])) * rr[tt][2 * hh + 1];
                    asm volatile("red.global.add.v2.f32 [%0], {%1,%2};"
                                 :: "l"(g_h + (size_t)a * 128 + col),
                                    "f"(h0), "f"(h1) : "memory");
                }
            }
        }
    }
}

// ---------------- K4: atom output GEMM via HMMA ----------------
#define K4_BH 0
#define K4_BL 34816
#define K4_AH 69632
#define K4_AL 87040
#define K4_SMEM 104448

__global__ __launch_bounds__(256, 1) void k_atom_out_hmma(
    const float* __restrict__ Watom, float* __restrict__ out, int N)
{
    extern __shared__ char smem[];
    uint32_t sb = smem_u32(smem);
    int tid = threadIdx.x;
    int l = tid & 31, w = tid >> 5;

    for (int i = tid; i < 8192; i += 256) {
        int k = i >> 6, n = (i & 63) * 2;
        float v0 = Watom[(size_t)k * 128 + n];
        float v1 = Watom[(size_t)k * 128 + n + 1];
        uint32_t hp, lp;
        split2(v0, v1, hp, lp);
        *(uint32_t*)(smem + K4_BH + k * 272 + n * 2) = hp;
        *(uint32_t*)(smem + K4_BL + k * 272 + n * 2) = lp;
    }

    int rowm = (l < 16) ? l : (l - 16);
    int colo = (l < 16) ? 0 : 8;
    int rb = w & 3, ch = w >> 2;
    int r_ = l >> 2, cc = (l & 3) * 2;

    uint32_t aH = sb + K4_AH + (rb * 16 + rowm) * 272 + colo * 2;
    uint32_t aL = aH + (K4_AL - K4_AH);
    uint32_t bH = sb + K4_BH + rowm * 272 + (ch * 64 + colo) * 2;
    uint32_t bL = bH + (K4_BL - K4_BH);

    int ntiles = (N + 63) >> 6;
    for (int tile = blockIdx.x; tile < ntiles; tile += gridDim.x) {
        int r0 = tile << 6;
        __syncthreads();

        #pragma unroll 4
        for (int it = 0; it < 8; it++) {
            int r = tid + it * 256;
            int e = r >> 5, kq = r & 31;
            float4 v = make_float4(0.f, 0.f, 0.f, 0.f);
            if (r0 + e < N) v = *(const float4*)(g_h + (size_t)(r0 + e) * 128 + kq * 4);
            uint32_t h01, l01, h23, l23;
            split2(v.x, v.y, h01, l01);
            split2(v.z, v.w, h23, l23);
            *(unsigned long long*)(smem + K4_AH + e * 272 + kq * 8) =
                ((unsigned long long)h23 << 32) | h01;
            *(unsigned long long*)(smem + K4_AL + e * 272 + kq * 8) =
                ((unsigned long long)l23 << 32) | l01;
        }
        __syncthreads();

        float acc[8][4];
        #pragma unroll
        for (int t = 0; t < 8; t++) {
            acc[t][0] = 0.f; acc[t][1] = 0.f; acc[t][2] = 0.f; acc[t][3] = 0.f;
        }
        #pragma unroll
        for (int ks = 0; ks < 8; ks++) {
            uint32_t ah0, ah1, ah2, ah3, al0, al1, al2, al3;
            LDSM4(ah0, ah1, ah2, ah3, aH + ks * 32);
            LDSM4(al0, al1, al2, al3, aL + ks * 32);
            uint32_t bkb = bH + ks * 16 * 272;
            uint32_t lkb = bL + ks * 16 * 272;
            #pragma unroll
            for (int p = 0; p < 4; p++) {
                uint32_t b0, b1, b2, b3, c0, c1, c2, c3;
                LDSM4T(b0, b1, b2, b3, bkb + p * 32);
                LDSM4T(c0, c1, c2, c3, lkb + p * 32);
                mma_bf16(acc[p * 2], ah0, ah1, ah2, ah3, b0, b1);
                mma_bf16(acc[p * 2], al0, al1, al2, al3, b0, b1);
                mma_bf16(acc[p * 2], ah0, ah1, ah2, ah3, c0, c1);
                mma_bf16(acc[p * 2 + 1], ah0, ah1, ah2, ah3, b2, b3);
                mma_bf16(acc[p * 2 + 1], al0, al1, al2, al3, b2, b3);
                mma_bf16(acc[p * 2 + 1], ah0, ah1, ah2, ah3, c2, c3);
            }
        }

        {
            int row0 = r0 + rb * 16 + r_;
            #pragma unroll
            for (int t = 0; t < 8; t++) {
                int col = ch * 64 + t * 8 + cc;
                if (row0 < N) {
                    *(float2*)(out + (size_t)row0 * 128 + col) =
                        make_float2(ssilu(acc[t][0]), ssilu(acc[t][1]));
                }
                if (row0 + 8 < N) {
                    *(float2*)(out + (size_t)(row0 + 8) * 128 + col) =
                        make_float2(ssilu(acc[t][2]), ssilu(acc[t][3]));
                }
            }
        }
    }
}

extern "C" void kernel_launch(void* const* d_in, const int* in_sizes, int n_in,
                              void* d_out, int out_size) {
    const float* m     = (const float*)d_in[0];
    const float* rbf   = (const float*)d_in[1];
    const float* cbf   = (const float*)d_in[2];
    const int*   id3ba = (const int*)d_in[3];
    const int*   id3ca = (const int*)d_in[4];
    const int*   idxt  = (const int*)d_in[5];
    const float* Wba   = (const float*)d_in[6];
    const float* Wrbf  = (const float*)d_in[7];
    const float* Wdown = (const float*)d_in[8];
    const float* Wcbf  = (const float*)d_in[9];
    const float* Wup   = (const float*)d_in[10];
    const float* Wra   = (const float*)d_in[11];
    const float* Watom = (const float*)d_in[12];

    int E = in_sizes[0] / 128;
    int T = in_sizes[2] / 16;
    int N = out_size / 128;

    cudaFuncSetAttribute(k_edge_down_hmma,
                         cudaFuncAttributeMaxDynamicSharedMemorySize, K1_SMEM);
    cudaFuncSetAttribute(k_atom_out_hmma,
                         cudaFuncAttributeMaxDynamicSharedMemorySize, K4_SMEM);

    k_zero<<<512, 256>>>((E * 16) / 4, (N * 128) / 4);
    k_edge_down_hmma<<<148, 256, K1_SMEM>>>(m, rbf, Wba, Wrbf, Wdown, E);
    k_triplet_hmma<<<(T + 127) / 128, 256>>>(cbf, id3ba, id3ca, Wcbf, T);
    k_edge_up_hmma<<<1184, 256>>>(m, rbf, idxt, Wup, Wra, E);
    k_atom_out_hmma<<<148, 256, K4_SMEM>>>(Watom, (float*)d_out, N);
}

// round 15
// speedup vs baseline: 1.0349x; 1.0349x over previous
#include <cuda_runtime.h>
#include <cstdint>

#define SSCALE 1.6666666666666667f

__device__ __forceinline__ float ssilu(float x) {
    float e = __expf(-x);
    return SSCALE * __fdividef(x, 1.0f + e);
}

// ---- bf16 split + mma helpers ----
__device__ __forceinline__ void split2(float v0, float v1, uint32_t& hi, uint32_t& lo) {
    asm("cvt.rn.bf16x2.f32 %0, %1, %2;" : "=r"(hi) : "f"(v1), "f"(v0));
    float h0 = __uint_as_float(hi << 16);
    float h1 = __uint_as_float(hi & 0xFFFF0000u);
    float r0 = v0 - h0, r1 = v1 - h1;
    asm("cvt.rn.bf16x2.f32 %0, %1, %2;" : "=r"(lo) : "f"(r1), "f"(r0));
}
__device__ __forceinline__ void mma_bf16(float* d, uint32_t a0, uint32_t a1,
                                         uint32_t a2, uint32_t a3,
                                         uint32_t b0, uint32_t b1) {
    asm("mma.sync.aligned.m16n8k16.row.col.f32.bf16.bf16.f32 "
        "{%0,%1,%2,%3}, {%4,%5,%6,%7}, {%8,%9}, {%0,%1,%2,%3};"
        : "+f"(d[0]), "+f"(d[1]), "+f"(d[2]), "+f"(d[3])
        : "r"(a0), "r"(a1), "r"(a2), "r"(a3), "r"(b0), "r"(b1));
}
#define LDSM4(d0, d1, d2, d3, a) asm volatile( \
    "ldmatrix.sync.aligned.m8n8.x4.shared.b16 {%0,%1,%2,%3}, [%4];" \
    : "=r"(d0), "=r"(d1), "=r"(d2), "=r"(d3) : "r"(a))
#define LDSM4T(d0, d1, d2, d3, a) asm volatile( \
    "ldmatrix.sync.aligned.m8n8.x4.trans.shared.b16 {%0,%1,%2,%3}, [%4];" \
    : "=r"(d0), "=r"(d1), "=r"(d2), "=r"(d3) : "r"(a))

__device__ __forceinline__ uint32_t smem_u32(const void* p) {
    uint32_t a;
    asm("{ .reg .u64 t; cvta.to.shared.u64 t, %1; cvt.u32.u64 %0, t; }"
        : "=r"(a) : "l"(p));
    return a;
}

#define E_MAX 700000
#define N_MAX 40000

__device__ __align__(16) float g_xdown[(size_t)E_MAX * 16];
__device__ __align__(16) float g_xe[(size_t)E_MAX * 16];
__device__ __align__(16) float g_h[(size_t)N_MAX * 128];

// ---------------- K1: edge dense + down projection (all HMMA) -------------
// Also zeroes g_xe / g_h in its prologue (overlapped with weight conversion).
#define OFF_BH  0
#define OFF_BL  34816
#define OFF_WRH 69632
#define OFF_WRL 73984
#define OFF_WDH 78336
#define OFF_WDL 82432
#define OFF_AH  86528
#define OFF_AL  103936
#define OFF_RBH 121344
#define OFF_RBL 124416
#define K1_SMEM 127488

__global__ __launch_bounds__(256, 1) void k_edge_down_hmma(
    const float* __restrict__ m, const float* __restrict__ rbf,
    const float* __restrict__ Wba, const float* __restrict__ Wrbf,
    const float* __restrict__ Wdown, int E, int N)
{
    extern __shared__ char smem[];
    uint32_t sb = smem_u32(smem);
    int tid = threadIdx.x;
    int l = tid & 31, w = tid >> 5;

    // zero scratch (grid-stride); DRAM writes drain behind the conversion work
    {
        int gi = blockIdx.x * 256 + tid;
        int gs = gridDim.x * 256;
        int n_xe4 = (E * 16) >> 2, n_h4 = (N * 128) >> 2;
        float4 z = make_float4(0.f, 0.f, 0.f, 0.f);
        for (int r = gi; r < n_xe4; r += gs) ((float4*)g_xe)[r] = z;
        for (int r = gi; r < n_h4; r += gs) ((float4*)g_h)[r] = z;
    }

    for (int i = tid; i < 8192; i += 256) {
        int k = i >> 6, n = (i & 63) * 2;
        float v0 = Wba[(size_t)k * 128 + n];
        float v1 = Wba[(size_t)k * 128 + n + 1];
        uint32_t hp, lp;
        split2(v0, v1, hp, lp);
        *(uint32_t*)(smem + OFF_BH + k * 272 + n * 2) = hp;
        *(uint32_t*)(smem + OFF_BL + k * 272 + n * 2) = lp;
    }
    for (int i = tid; i < 1024; i += 256) {
        int k = i >> 6, n = (i & 63) * 2;
        float v0 = Wrbf[(size_t)k * 128 + n];
        float v1 = Wrbf[(size_t)k * 128 + n + 1];
        uint32_t hp, lp;
        split2(v0, v1, hp, lp);
        *(uint32_t*)(smem + OFF_WRH + k * 272 + n * 2) = hp;
        *(uint32_t*)(smem + OFF_WRL + k * 272 + n * 2) = lp;
    }
    for (int i = tid; i < 1024; i += 256) {
        int k = i >> 3, n = (i & 7) * 2;
        float v0 = Wdown[(size_t)k * 16 + n];
        float v1 = Wdown[(size_t)k * 16 + n + 1];
        uint32_t hp, lp;
        split2(v0, v1, hp, lp);
        *(uint32_t*)(smem + OFF_WDH + k * 32 + n * 2) = hp;
        *(uint32_t*)(smem + OFF_WDL + k * 32 + n * 2) = lp;
    }

    int rowm = (l < 16) ? l : (l - 16);
    int colo = (l < 16) ? 0 : 8;
    int rb = w & 3, ch = w >> 2;
    int r_ = l >> 2, cc2 = (l & 3) * 2;

    uint32_t aH = sb + OFF_AH + (rb * 16 + rowm) * 272 + colo * 2;
    uint32_t aL = aH + (OFF_AL - OFF_AH);
    uint32_t rH = sb + OFF_RBH + (rb * 16 + rowm) * 48 + colo * 2;
    uint32_t rL = rH + (OFF_RBL - OFF_RBH);
    uint32_t bH = sb + OFF_BH + rowm * 272 + (ch * 64 + colo) * 2;
    uint32_t bL = bH + (OFF_BL - OFF_BH);
    uint32_t wrH = sb + OFF_WRH + rowm * 272 + (ch * 64 + colo) * 2;
    uint32_t wrL = wrH + (OFF_WRL - OFF_WRH);
    uint32_t wdH = sb + OFF_WDH + rowm * 32 + colo * 2;
    uint32_t wdL = wdH + (OFF_WDL - OFF_WDH);

    char* sXH = smem + OFF_AH;
    char* sXL = smem + OFF_AL;

    int ntiles = (E + 63) >> 6;
    for (int tile = blockIdx.x; tile < ntiles; tile += gridDim.x) {
        int e0 = tile << 6;
        __syncthreads();

        #pragma unroll 4
        for (int it = 0; it < 8; it++) {
            int r = tid + it * 256;
            int e = r >> 5, kq = r & 31;
            float4 v = make_float4(0.f, 0.f, 0.f, 0.f);
            if (e0 + e < E) v = *(const float4*)(m + (size_t)(e0 + e) * 128 + kq * 4);
            uint32_t h01, l01, h23, l23;
            split2(v.x, v.y, h01, l01);
            split2(v.z, v.w, h23, l23);
            *(unsigned long long*)(smem + OFF_AH + e * 272 + kq * 8) =
                ((unsigned long long)h23 << 32) | h01;
            *(unsigned long long*)(smem + OFF_AL + e * 272 + kq * 8) =
                ((unsigned long long)l23 << 32) | l01;
        }
        {
            int e = tid >> 2, kp = tid & 3;
            #pragma unroll
            for (int half = 0; half < 2; half++) {
                int k = (kp + half * 4) * 2;
                float2 v = make_float2(0.f, 0.f);
                if (e0 + e < E) v = *(const float2*)(rbf + (size_t)(e0 + e) * 16 + k);
                uint32_t hp, lp;
                split2(v.x, v.y, hp, lp);
                *(uint32_t*)(smem + OFF_RBH + e * 48 + k * 2) = hp;
                *(uint32_t*)(smem + OFF_RBL + e * 48 + k * 2) = lp;
            }
        }
        __syncthreads();

        float rw[8][4];
        #pragma unroll
        for (int t = 0; t < 8; t++) {
            rw[t][0] = 0.f; rw[t][1] = 0.f; rw[t][2] = 0.f; rw[t][3] = 0.f;
        }
        {
            uint32_t ra0, ra1, ra2, ra3, rl0, rl1, rl2, rl3;
            LDSM4(ra0, ra1, ra2, ra3, rH);
            LDSM4(rl0, rl1, rl2, rl3, rL);
            #pragma unroll
            for (int p = 0; p < 4; p++) {
                uint32_t b0, b1, b2, b3, c0, c1, c2, c3;
                LDSM4T(b0, b1, b2, b3, wrH + p * 32);
                LDSM4T(c0, c1, c2, c3, wrL + p * 32);
                mma_bf16(rw[p * 2], ra0, ra1, ra2, ra3, b0, b1);
                mma_bf16(rw[p * 2], rl0, rl1, rl2, rl3, b0, b1);
                mma_bf16(rw[p * 2], ra0, ra1, ra2, ra3, c0, c1);
                mma_bf16(rw[p * 2 + 1], ra0, ra1, ra2, ra3, b2, b3);
                mma_bf16(rw[p * 2 + 1], rl0, rl1, rl2, rl3, b2, b3);
                mma_bf16(rw[p * 2 + 1], ra0, ra1, ra2, ra3, c2, c3);
            }
        }

        float acc[8][4];
        #pragma unroll
        for (int t = 0; t < 8; t++) {
            acc[t][0] = 0.f; acc[t][1] = 0.f; acc[t][2] = 0.f; acc[t][3] = 0.f;
        }
        #pragma unroll
        for (int ks = 0; ks < 8; ks++) {
            uint32_t ah0, ah1, ah2, ah3, al0, al1, al2, al3;
            LDSM4(ah0, ah1, ah2, ah3, aH + ks * 32);
            LDSM4(al0, al1, al2, al3, aL + ks * 32);
            uint32_t bkb = bH + ks * 16 * 272;
            uint32_t lkb = bL + ks * 16 * 272;
            #pragma unroll
            for (int p = 0; p < 4; p++) {
                uint32_t b0, b1, b2, b3, c0, c1, c2, c3;
                LDSM4T(b0, b1, b2, b3, bkb + p * 32);
                LDSM4T(c0, c1, c2, c3, lkb + p * 32);
                mma_bf16(acc[p * 2], ah0, ah1, ah2, ah3, b0, b1);
                mma_bf16(acc[p * 2], al0, al1, al2, al3, b0, b1);
                mma_bf16(acc[p * 2], ah0, ah1, ah2, ah3, c0, c1);
                mma_bf16(acc[p * 2 + 1], ah0, ah1, ah2, ah3, b2, b3);
                mma_bf16(acc[p * 2 + 1], al0, al1, al2, al3, b2, b3);
                mma_bf16(acc[p * 2 + 1], ah0, ah1, ah2, ah3, c2, c3);
            }
        }

        __syncthreads();

        {
            int row0 = rb * 16 + r_;
            #pragma unroll
            for (int t = 0; t < 8; t++) {
                int colb = (ch * 64 + t * 8 + cc2) * 2;
                float x0 = ssilu(acc[t][0]) * rw[t][0];
                float x1 = ssilu(acc[t][1]) * rw[t][1];
                float x2 = ssilu(acc[t][2]) * rw[t][2];
                float x3 = ssilu(acc[t][3]) * rw[t][3];
                uint32_t hp, lp;
                split2(x0, x1, hp, lp);
                *(uint32_t*)(sXH + row0 * 272 + colb) = hp;
                *(uint32_t*)(sXL + row0 * 272 + colb) = lp;
                split2(x2, x3, hp, lp);
                *(uint32_t*)(sXH + (row0 + 8) * 272 + colb) = hp;
                *(uint32_t*)(sXL + (row0 + 8) * 272 + colb) = lp;
            }
        }
        __syncthreads();

        if (w < 4) {
            float d0[4] = {0.f, 0.f, 0.f, 0.f}, d1[4] = {0.f, 0.f, 0.f, 0.f};
            #pragma unroll
            for (int ks = 0; ks < 8; ks++) {
                uint32_t xh0, xh1, xh2, xh3, xl0, xl1, xl2, xl3;
                LDSM4(xh0, xh1, xh2, xh3, aH + ks * 32);
                LDSM4(xl0, xl1, xl2, xl3, aL + ks * 32);
                uint32_t b0, b1, b2, b3, c0, c1, c2, c3;
                LDSM4T(b0, b1, b2, b3, wdH + ks * 512);
                LDSM4T(c0, c1, c2, c3, wdL + ks * 512);
                mma_bf16(d0, xh0, xh1, xh2, xh3, b0, b1);
                mma_bf16(d0, xl0, xl1, xl2, xl3, b0, b1);
                mma_bf16(d0, xh0, xh1, xh2, xh3, c0, c1);
                mma_bf16(d1, xh0, xh1, xh2, xh3, b2, b3);
                mma_bf16(d1, xl0, xl1, xl2, xl3, b2, b3);
                mma_bf16(d1, xh0, xh1, xh2, xh3, c2, c3);
            }
            int e_row = e0 + rb * 16 + r_;
            if (e_row < E) {
                *(float2*)(g_xdown + (size_t)e_row * 16 + cc2) = make_float2(d0[0], d0[1]);
                *(float2*)(g_xdown + (size_t)e_row * 16 + 8 + cc2) = make_float2(d1[0], d1[1]);
            }
            if (e_row + 8 < E) {
                *(float2*)(g_xdown + (size_t)(e_row + 8) * 16 + cc2) = make_float2(d0[2], d0[3]);
                *(float2*)(g_xdown + (size_t)(e_row + 8) * 16 + 8 + cc2) = make_float2(d1[2], d1[3]);
            }
        }
    }
}

// ---------------- K2: triplet stage via HMMA (pipelined gather) -----------
#define T3_CBH 0
#define T3_CBL 4096
#define T3_WCH 8192
#define T3_WCL 8704
#define T3_XD  9216
#define T3_BA  17408
#define T3_CA  17920
#define T3_SMEM 18432

__global__ __launch_bounds__(256) void k_triplet_hmma(
    const float* __restrict__ cbf,
    const int* __restrict__ ba, const int* __restrict__ ca,
    const float* __restrict__ Wcbf, int T)
{
    __shared__ __align__(16) char smem[T3_SMEM];
    uint32_t sb = smem_u32(smem);
    int tid = threadIdx.x;
    int l = tid & 31, w = tid >> 5;
    int t0 = blockIdx.x << 7;

    int* sBa = (int*)(smem + T3_BA);
    int* sCa = (int*)(smem + T3_CA);
    float* sXd = (float*)(smem + T3_XD);

    if (tid < 128) {
        int k = tid >> 3, n = (tid & 7) * 2;
        float v0 = Wcbf[k * 16 + n], v1 = Wcbf[k * 16 + n + 1];
        uint32_t hp, lp;
        split2(v0, v1, hp, lp);
        *(uint32_t*)(smem + T3_WCH + k * 32 + n * 2) = hp;
        *(uint32_t*)(smem + T3_WCL + k * 32 + n * 2) = lp;
    } else {
        int ti = tid - 128;
        int t = t0 + ti;
        bool ok = t < T;
        sBa[ti] = ok ? ba[t] : 0;
        sCa[ti] = ok ? ca[t] : -1;
    }
    __syncthreads();

    int gr = tid >> 1, ghalf = tid & 1;
    int gb = sBa[gr];
    float4 g0 = *(const float4*)(g_xdown + (size_t)gb * 16 + ghalf * 8);
    float4 g1 = *(const float4*)(g_xdown + (size_t)gb * 16 + ghalf * 8 + 4);

    {
        int e = tid >> 1, q = tid & 1;
        int t = t0 + e;
        bool ok = t < T;
        #pragma unroll
        for (int j = 0; j < 2; j++) {
            int qq = q * 2 + j;
            float4 v = make_float4(0.f, 0.f, 0.f, 0.f);
            if (ok) v = *(const float4*)(cbf + (size_t)t * 16 + qq * 4);
            uint32_t h01, l01, h23, l23;
            split2(v.x, v.y, h01, l01);
            split2(v.z, v.w, h23, l23);
            *(unsigned long long*)(smem + T3_CBH + e * 32 + qq * 8) =
                ((unsigned long long)h23 << 32) | h01;
            *(unsigned long long*)(smem + T3_CBL + e * 32 + qq * 8) =
                ((unsigned long long)l23 << 32) | l01;
        }
    }
    *(float4*)&sXd[gr * 16 + ghalf * 8] = g0;
    *(float4*)&sXd[gr * 16 + ghalf * 8 + 4] = g1;
    __syncthreads();

    int rowm = (l < 16) ? l : (l - 16);
    int colo = (l < 16) ? 0 : 8;
    int r_ = l >> 2, cc = (l & 3) * 2;

    uint32_t aH = sb + T3_CBH + (w * 16 + rowm) * 32 + colo * 2;
    uint32_t aL = aH + (T3_CBL - T3_CBH);
    uint32_t bHa = sb + T3_WCH + rowm * 32 + colo * 2;
    uint32_t bLa = bHa + (T3_WCL - T3_WCH);

    uint32_t ah0, ah1, ah2, ah3, al0, al1, al2, al3;
    uint32_t b0, b1, b2, b3, c0, c1, c2, c3;
    LDSM4(ah0, ah1, ah2, ah3, aH);
    LDSM4(al0, al1, al2, al3, aL);
    LDSM4T(b0, b1, b2, b3, bHa);
    LDSM4T(c0, c1, c2, c3, bLa);

    float u[2][4];
    u[0][0]=u[0][1]=u[0][2]=u[0][3]=0.f;
    u[1][0]=u[1][1]=u[1][2]=u[1][3]=0.f;
    mma_bf16(u[0], ah0, ah1, ah2, ah3, b0, b1);
    mma_bf16(u[0], al0, al1, al2, al3, b0, b1);
    mma_bf16(u[0], ah0, ah1, ah2, ah3, c0, c1);
    mma_bf16(u[1], ah0, ah1, ah2, ah3, b2, b3);
    mma_bf16(u[1], al0, al1, al2, al3, b2, b3);
    mma_bf16(u[1], ah0, ah1, ah2, ah3, c2, c3);

    #pragma unroll
    for (int t = 0; t < 2; t++) {
        int col = t * 8 + cc;
        #pragma unroll
        for (int hh = 0; hh < 2; hh++) {
            int row = w * 16 + r_ + 8 * hh;
            int c_ = sCa[row];
            if (c_ < 0) continue;
            float2 xd = *(float2*)&sXd[row * 16 + col];
            float v0 = u[t][2 * hh] * xd.x;
            float v1 = u[t][2 * hh + 1] * xd.y;
            asm volatile("red.global.add.v2.f32 [%0], {%1,%2};"
                         :: "l"(g_xe + (size_t)c_ * 16 + col),
                            "f"(v0), "f"(v1) : "memory");
        }
    }
}

// ---------------- K3: edge up-projection + atom scatter (HMMA, occ4) ------
#define OFF2_UPH 0
#define OFF2_UPL 4352
#define OFF2_RAH 8704
#define OFF2_RAL 13056
#define OFF2_XEH 17408
#define OFF2_XEL 20480
#define OFF2_RBH 23552
#define OFF2_RBL 26624
#define OFF2_IDX 29696
#define K3_SMEM  29952

__global__ __launch_bounds__(256, 4) void k_edge_up_hmma(
    const float* __restrict__ m, const float* __restrict__ rbf,
    const int* __restrict__ idxt,
    const float* __restrict__ Wup, const float* __restrict__ Wra, int E)
{
    __shared__ __align__(16) char smem[K3_SMEM];
    uint32_t sb = smem_u32(smem);
    int tid = threadIdx.x;
    int l = tid & 31, w = tid >> 5;

    for (int i = tid; i < 1024; i += 256) {
        int k = i >> 6, n = (i & 63) * 2;
        float v0 = Wup[(size_t)k * 128 + n], v1 = Wup[(size_t)k * 128 + n + 1];
        uint32_t hp, lp;
        split2(v0, v1, hp, lp);
        *(uint32_t*)(smem + OFF2_UPH + k * 272 + n * 2) = hp;
        *(uint32_t*)(smem + OFF2_UPL + k * 272 + n * 2) = lp;
        v0 = Wra[(size_t)k * 128 + n]; v1 = Wra[(size_t)k * 128 + n + 1];
        split2(v0, v1, hp, lp);
        *(uint32_t*)(smem + OFF2_RAH + k * 272 + n * 2) = hp;
        *(uint32_t*)(smem + OFF2_RAL + k * 272 + n * 2) = lp;
    }

    int rowm = (l < 16) ? l : (l - 16);
    int colo = (l < 16) ? 0 : 8;
    int rb = w & 3, ch = w >> 2;
    int r_ = l >> 2, cc = (l & 3) * 2;

    uint32_t xH = sb + OFF2_XEH + (rb * 16 + rowm) * 48 + colo * 2;
    uint32_t xL = xH + (OFF2_XEL - OFF2_XEH);
    uint32_t rbH = sb + OFF2_RBH + (rb * 16 + rowm) * 48 + colo * 2;
    uint32_t rbL = rbH + (OFF2_RBL - OFF2_RBH);
    uint32_t bUH = sb + OFF2_UPH + rowm * 272 + (ch * 64 + colo) * 2;
    uint32_t bUL = bUH + (OFF2_UPL - OFF2_UPH);
    uint32_t bRH = sb + OFF2_RAH + rowm * 272 + (ch * 64 + colo) * 2;
    uint32_t bRL = bRH + (OFF2_RAL - OFF2_RAH);
    int* sIdx = (int*)(smem + OFF2_IDX);

    int ntiles = (E + 63) >> 6;
    for (int tile = blockIdx.x; tile < ntiles; tile += gridDim.x) {
        int e0 = tile << 6;
        __syncthreads();

        {
            int e = tid >> 2, q = tid & 3;
            float4 vx = make_float4(0.f, 0.f, 0.f, 0.f), vr = vx;
            if (e0 + e < E) {
                vx = *(const float4*)(g_xe + (size_t)(e0 + e) * 16 + q * 4);
                vr = *(const float4*)(rbf + (size_t)(e0 + e) * 16 + q * 4);
            }
            uint32_t h01, l01, h23, l23;
            split2(vx.x, vx.y, h01, l01); split2(vx.z, vx.w, h23, l23);
            *(unsigned long long*)(smem + OFF2_XEH + e * 48 + q * 8) =
                ((unsigned long long)h23 << 32) | h01;
            *(unsigned long long*)(smem + OFF2_XEL + e * 48 + q * 8) =
                ((unsigned long long)l23 << 32) | l01;
            split2(vr.x, vr.y, h01, l01); split2(vr.z, vr.w, h23, l23);
            *(unsigned long long*)(smem + OFF2_RBH + e * 48 + q * 8) =
                ((unsigned long long)h23 << 32) | h01;
            *(unsigned long long*)(smem + OFF2_RBL + e * 48 + q * 8) =
                ((unsigned long long)l23 << 32) | l01;
        }
        if (tid < 64) sIdx[tid] = (e0 + tid < E) ? idxt[e0 + tid] : -1;
        __syncthreads();

        uint32_t xh0, xh1, xh2, xh3, xl0, xl1, xl2, xl3;
        uint32_t rh0, rh1, rh2, rh3, rl0, rl1, rl2, rl3;
        LDSM4(xh0, xh1, xh2, xh3, xH);
        LDSM4(xl0, xl1, xl2, xl3, xL);
        LDSM4(rh0, rh1, rh2, rh3, rbH);
        LDSM4(rl0, rl1, rl2, rl3, rbL);

        #pragma unroll
        for (int p = 0; p < 4; p++) {
            float u[2][4], rr[2][4];
            u[0][0]=u[0][1]=u[0][2]=u[0][3]=0.f;
            u[1][0]=u[1][1]=u[1][2]=u[1][3]=0.f;
            rr[0][0]=rr[0][1]=rr[0][2]=rr[0][3]=0.f;
            rr[1][0]=rr[1][1]=rr[1][2]=rr[1][3]=0.f;
            {
                uint32_t b0, b1, b2, b3, c0, c1, c2, c3;
                LDSM4T(b0, b1, b2, b3, bUH + p * 32);
                LDSM4T(c0, c1, c2, c3, bUL + p * 32);
                mma_bf16(u[0], xh0, xh1, xh2, xh3, b0, b1);
                mma_bf16(u[0], xl0, xl1, xl2, xl3, b0, b1);
                mma_bf16(u[0], xh0, xh1, xh2, xh3, c0, c1);
                mma_bf16(u[1], xh0, xh1, xh2, xh3, b2, b3);
                mma_bf16(u[1], xl0, xl1, xl2, xl3, b2, b3);
                mma_bf16(u[1], xh0, xh1, xh2, xh3, c2, c3);
            }
            {
                uint32_t b0, b1, b2, b3, c0, c1, c2, c3;
                LDSM4T(b0, b1, b2, b3, bRH + p * 32);
                LDSM4T(c0, c1, c2, c3, bRL + p * 32);
                mma_bf16(rr[0], rh0, rh1, rh2, rh3, b0, b1);
                mma_bf16(rr[0], rl0, rl1, rl2, rl3, b0, b1);
                mma_bf16(rr[0], rh0, rh1, rh2, rh3, c0, c1);
                mma_bf16(rr[1], rh0, rh1, rh2, rh3, b2, b3);
                mma_bf16(rr[1], rl0, rl1, rl2, rl3, b2, b3);
                mma_bf16(rr[1], rh0, rh1, rh2, rh3, c2, c3);
            }
            #pragma unroll
            for (int tt = 0; tt < 2; tt++) {
                int col = ch * 64 + (2 * p + tt) * 8 + cc;
                #pragma unroll
                for (int hh = 0; hh < 2; hh++) {
                    int row = rb * 16 + r_ + 8 * hh;
                    int a = sIdx[row];
                    if (a < 0) continue;
                    float2 mm = *(const float2*)(m + (size_t)(e0 + row) * 128 + col);
                    float h0 = (mm.x + ssilu(u[tt][2 * hh])) * rr[tt][2 * hh];
                    float h1 = (mm.y + ssilu(u[tt][2 * hh + 1])) * rr[tt][2 * hh + 1];
                    asm volatile("red.global.add.v2.f32 [%0], {%1,%2};"
                                 :: "l"(g_h + (size_t)a * 128 + col),
                                    "f"(h0), "f"(h1) : "memory");
                }
            }
        }
    }
}

// ---------------- K4: atom output GEMM via HMMA ----------------
#define K4_BH 0
#define K4_BL 34816
#define K4_AH 69632
#define K4_AL 87040
#define K4_SMEM 104448

__global__ __launch_bounds__(256, 1) void k_atom_out_hmma(
    const float* __restrict__ Watom, float* __restrict__ out, int N)
{
    extern __shared__ char smem[];
    uint32_t sb = smem_u32(smem);
    int tid = threadIdx.x;
    int l = tid & 31, w = tid >> 5;

    for (int i = tid; i < 8192; i += 256) {
        int k = i >> 6, n = (i & 63) * 2;
        float v0 = Watom[(size_t)k * 128 + n];
        float v1 = Watom[(size_t)k * 128 + n + 1];
        uint32_t hp, lp;
        split2(v0, v1, hp, lp);
        *(uint32_t*)(smem + K4_BH + k * 272 + n * 2) = hp;
        *(uint32_t*)(smem + K4_BL + k * 272 + n * 2) = lp;
    }

    int rowm = (l < 16) ? l : (l - 16);
    int colo = (l < 16) ? 0 : 8;
    int rb = w & 3, ch = w >> 2;
    int r_ = l >> 2, cc = (l & 3) * 2;

    uint32_t aH = sb + K4_AH + (rb * 16 + rowm) * 272 + colo * 2;
    uint32_t aL = aH + (K4_AL - K4_AH);
    uint32_t bH = sb + K4_BH + rowm * 272 + (ch * 64 + colo) * 2;
    uint32_t bL = bH + (K4_BL - K4_BH);

    int ntiles = (N + 63) >> 6;
    for (int tile = blockIdx.x; tile < ntiles; tile += gridDim.x) {
        int r0 = tile << 6;
        __syncthreads();

        #pragma unroll 4
        for (int it = 0; it < 8; it++) {
            int r = tid + it * 256;
            int e = r >> 5, kq = r & 31;
            float4 v = make_float4(0.f, 0.f, 0.f, 0.f);
            if (r0 + e < N) v = *(const float4*)(g_h + (size_t)(r0 + e) * 128 + kq * 4);
            uint32_t h01, l01, h23, l23;
            split2(v.x, v.y, h01, l01);
            split2(v.z, v.w, h23, l23);
            *(unsigned long long*)(smem + K4_AH + e * 272 + kq * 8) =
                ((unsigned long long)h23 << 32) | h01;
            *(unsigned long long*)(smem + K4_AL + e * 272 + kq * 8) =
                ((unsigned long long)l23 << 32) | l01;
        }
        __syncthreads();

        float acc[8][4];
        #pragma unroll
        for (int t = 0; t < 8; t++) {
            acc[t][0] = 0.f; acc[t][1] = 0.f; acc[t][2] = 0.f; acc[t][3] = 0.f;
        }
        #pragma unroll
        for (int ks = 0; ks < 8; ks++) {
            uint32_t ah0, ah1, ah2, ah3, al0, al1, al2, al3;
            LDSM4(ah0, ah1, ah2, ah3, aH + ks * 32);
            LDSM4(al0, al1, al2, al3, aL + ks * 32);
            uint32_t bkb = bH + ks * 16 * 272;
            uint32_t lkb = bL + ks * 16 * 272;
            #pragma unroll
            for (int p = 0; p < 4; p++) {
                uint32_t b0, b1, b2, b3, c0, c1, c2, c3;
                LDSM4T(b0, b1, b2, b3, bkb + p * 32);
                LDSM4T(c0, c1, c2, c3, lkb + p * 32);
                mma_bf16(acc[p * 2], ah0, ah1, ah2, ah3, b0, b1);
                mma_bf16(acc[p * 2], al0, al1, al2, al3, b0, b1);
                mma_bf16(acc[p * 2], ah0, ah1, ah2, ah3, c0, c1);
                mma_bf16(acc[p * 2 + 1], ah0, ah1, ah2, ah3, b2, b3);
                mma_bf16(acc[p * 2 + 1], al0, al1, al2, al3, b2, b3);
                mma_bf16(acc[p * 2 + 1], ah0, ah1, ah2, ah3, c2, c3);
            }
        }

        {
            int row0 = r0 + rb * 16 + r_;
            #pragma unroll
            for (int t = 0; t < 8; t++) {
                int col = ch * 64 + t * 8 + cc;
                if (row0 < N) {
                    *(float2*)(out + (size_t)row0 * 128 + col) =
                        make_float2(ssilu(acc[t][0]), ssilu(acc[t][1]));
                }
                if (row0 + 8 < N) {
                    *(float2*)(out + (size_t)(row0 + 8) * 128 + col) =
                        make_float2(ssilu(acc[t][2]), ssilu(acc[t][3]));
                }
            }
        }
    }
}

extern "C" void kernel_launch(void* const* d_in, const int* in_sizes, int n_in,
                              void* d_out, int out_size) {
    const float* m     = (const float*)d_in[0];
    const float* rbf   = (const float*)d_in[1];
    const float* cbf   = (const float*)d_in[2];
    const int*   id3ba = (const int*)d_in[3];
    const int*   id3ca = (const int*)d_in[4];
    const int*   idxt  = (const int*)d_in[5];
    const float* Wba   = (const float*)d_in[6];
    const float* Wrbf  = (const float*)d_in[7];
    const float* Wdown = (const float*)d_in[8];
    const float* Wcbf  = (const float*)d_in[9];
    const float* Wup   = (const float*)d_in[10];
    const float* Wra   = (const float*)d_in[11];
    const float* Watom = (const float*)d_in[12];

    int E = in_sizes[0] / 128;
    int T = in_sizes[2] / 16;
    int N = out_size / 128;

    cudaFuncSetAttribute(k_edge_down_hmma,
                         cudaFuncAttributeMaxDynamicSharedMemorySize, K1_SMEM);
    cudaFuncSetAttribute(k_atom_out_hmma,
                         cudaFuncAttributeMaxDynamicSharedMemorySize, K4_SMEM);

    k_edge_down_hmma<<<148, 256, K1_SMEM>>>(m, rbf, Wba, Wrbf, Wdown, E, N);
    k_triplet_hmma<<<(T + 127) / 128, 256>>>(cbf, id3ba, id3ca, Wcbf, T);
    k_edge_up_hmma<<<1184, 256>>>(m, rbf, idxt, Wup, Wra, E);
    k_atom_out_hmma<<<148, 256, K4_SMEM>>>(Watom, (float*)d_out, N);
}

// round 16
// speedup vs baseline: 1.1777x; 1.1380x over previous
#include <cuda_runtime.h>
#include <cstdint>

#define SSCALE 1.6666666666666667f

__device__ __forceinline__ float ssilu(float x) {
    float e = __expf(-x);
    return SSCALE * __fdividef(x, 1.0f + e);
}

// ---- bf16 split + mma helpers ----
__device__ __forceinline__ void split2(float v0, float v1, uint32_t& hi, uint32_t& lo) {
    asm("cvt.rn.bf16x2.f32 %0, %1, %2;" : "=r"(hi) : "f"(v1), "f"(v0));
    float h0 = __uint_as_float(hi << 16);
    float h1 = __uint_as_float(hi & 0xFFFF0000u);
    float r0 = v0 - h0, r1 = v1 - h1;
    asm("cvt.rn.bf16x2.f32 %0, %1, %2;" : "=r"(lo) : "f"(r1), "f"(r0));
}
__device__ __forceinline__ void mma_bf16(float* d, uint32_t a0, uint32_t a1,
                                         uint32_t a2, uint32_t a3,
                                         uint32_t b0, uint32_t b1) {
    asm("mma.sync.aligned.m16n8k16.row.col.f32.bf16.bf16.f32 "
        "{%0,%1,%2,%3}, {%4,%5,%6,%7}, {%8,%9}, {%0,%1,%2,%3};"
        : "+f"(d[0]), "+f"(d[1]), "+f"(d[2]), "+f"(d[3])
        : "r"(a0), "r"(a1), "r"(a2), "r"(a3), "r"(b0), "r"(b1));
}
#define LDSM4(d0, d1, d2, d3, a) asm volatile( \
    "ldmatrix.sync.aligned.m8n8.x4.shared.b16 {%0,%1,%2,%3}, [%4];" \
    : "=r"(d0), "=r"(d1), "=r"(d2), "=r"(d3) : "r"(a))
#define LDSM4T(d0, d1, d2, d3, a) asm volatile( \
    "ldmatrix.sync.aligned.m8n8.x4.trans.shared.b16 {%0,%1,%2,%3}, [%4];" \
    : "=r"(d0), "=r"(d1), "=r"(d2), "=r"(d3) : "r"(a))

__device__ __forceinline__ uint32_t smem_u32(const void* p) {
    uint32_t a;
    asm("{ .reg .u64 t; cvta.to.shared.u64 t, %1; cvt.u32.u64 %0, t; }"
        : "=r"(a) : "l"(p));
    return a;
}

#define E_MAX 700000
#define N_MAX 40000

__device__ __align__(16) float g_xdown[(size_t)E_MAX * 16];
__device__ __align__(16) float g_xe[(size_t)E_MAX * 16];
__device__ __align__(16) float g_h[(size_t)N_MAX * 128];

// ---------------- K1: edge dense + down projection (all HMMA) -------------
// Zeroes g_xe/g_h in prologue; software-pipelines the m/rbf gmem loads.
#define OFF_BH  0
#define OFF_BL  34816
#define OFF_WRH 69632
#define OFF_WRL 73984
#define OFF_WDH 78336
#define OFF_WDL 82432
#define OFF_AH  86528
#define OFF_AL  103936
#define OFF_RBH 121344
#define OFF_RBL 124416
#define K1_SMEM 127488

__global__ __launch_bounds__(256, 1) void k_edge_down_hmma(
    const float* __restrict__ m, const float* __restrict__ rbf,
    const float* __restrict__ Wba, const float* __restrict__ Wrbf,
    const float* __restrict__ Wdown, int E, int N)
{
    extern __shared__ char smem[];
    uint32_t sb = smem_u32(smem);
    int tid = threadIdx.x;
    int l = tid & 31, w = tid >> 5;

    // zero scratch (grid-stride); drains behind conversion work
    {
        int gi = blockIdx.x * 256 + tid;
        int gs = gridDim.x * 256;
        int n_xe4 = (E * 16) >> 2, n_h4 = (N * 128) >> 2;
        float4 z = make_float4(0.f, 0.f, 0.f, 0.f);
        for (int r = gi; r < n_xe4; r += gs) ((float4*)g_xe)[r] = z;
        for (int r = gi; r < n_h4; r += gs) ((float4*)g_h)[r] = z;
    }

    for (int i = tid; i < 8192; i += 256) {
        int k = i >> 6, n = (i & 63) * 2;
        float v0 = Wba[(size_t)k * 128 + n];
        float v1 = Wba[(size_t)k * 128 + n + 1];
        uint32_t hp, lp;
        split2(v0, v1, hp, lp);
        *(uint32_t*)(smem + OFF_BH + k * 272 + n * 2) = hp;
        *(uint32_t*)(smem + OFF_BL + k * 272 + n * 2) = lp;
    }
    for (int i = tid; i < 1024; i += 256) {
        int k = i >> 6, n = (i & 63) * 2;
        float v0 = Wrbf[(size_t)k * 128 + n];
        float v1 = Wrbf[(size_t)k * 128 + n + 1];
        uint32_t hp, lp;
        split2(v0, v1, hp, lp);
        *(uint32_t*)(smem + OFF_WRH + k * 272 + n * 2) = hp;
        *(uint32_t*)(smem + OFF_WRL + k * 272 + n * 2) = lp;
    }
    for (int i = tid; i < 1024; i += 256) {
        int k = i >> 3, n = (i & 7) * 2;
        float v0 = Wdown[(size_t)k * 16 + n];
        float v1 = Wdown[(size_t)k * 16 + n + 1];
        uint32_t hp, lp;
        split2(v0, v1, hp, lp);
        *(uint32_t*)(smem + OFF_WDH + k * 32 + n * 2) = hp;
        *(uint32_t*)(smem + OFF_WDL + k * 32 + n * 2) = lp;
    }

    int rowm = (l < 16) ? l : (l - 16);
    int colo = (l < 16) ? 0 : 8;
    int rb = w & 3, ch = w >> 2;
    int r_ = l >> 2, cc2 = (l & 3) * 2;

    uint32_t aH = sb + OFF_AH + (rb * 16 + rowm) * 272 + colo * 2;
    uint32_t aL = aH + (OFF_AL - OFF_AH);
    uint32_t rH = sb + OFF_RBH + (rb * 16 + rowm) * 48 + colo * 2;
    uint32_t rL = rH + (OFF_RBL - OFF_RBH);
    uint32_t bH = sb + OFF_BH + rowm * 272 + (ch * 64 + colo) * 2;
    uint32_t bL = bH + (OFF_BL - OFF_BH);
    uint32_t wrH = sb + OFF_WRH + rowm * 272 + (ch * 64 + colo) * 2;
    uint32_t wrL = wrH + (OFF_WRL - OFF_WRH);
    uint32_t wdH = sb + OFF_WDH + rowm * 32 + colo * 2;
    uint32_t wdL = wdH + (OFF_WDL - OFF_WDH);

    char* sXH = smem + OFF_AH;
    char* sXL = smem + OFF_AL;

    // per-thread load indices for m/rbf tiles
    int m_e[8], m_kq[8];
    #pragma unroll
    for (int it = 0; it < 8; it++) {
        int r = tid + it * 256;
        m_e[it] = r >> 5;
        m_kq[it] = r & 31;
    }
    int rb_e = tid >> 2, rb_kp = tid & 3;

    int ntiles = (E + 63) >> 6;
    float4 pm[8];
    float2 prb[2];

    // prefetch first tile
    {
        int e0 = blockIdx.x << 6;
        #pragma unroll
        for (int it = 0; it < 8; it++) {
            pm[it] = make_float4(0.f, 0.f, 0.f, 0.f);
            if (e0 + m_e[it] < E)
                pm[it] = *(const float4*)(m + (size_t)(e0 + m_e[it]) * 128 + m_kq[it] * 4);
        }
        #pragma unroll
        for (int half = 0; half < 2; half++) {
            int k = (rb_kp + half * 4) * 2;
            prb[half] = make_float2(0.f, 0.f);
            if (e0 + rb_e < E)
                prb[half] = *(const float2*)(rbf + (size_t)(e0 + rb_e) * 16 + k);
        }
    }

    for (int tile = blockIdx.x; tile < ntiles; tile += gridDim.x) {
        int e0 = tile << 6;
        __syncthreads();

        // store prefetched m tile (split + STS, no LDG stall)
        #pragma unroll
        for (int it = 0; it < 8; it++) {
            float4 v = pm[it];
            uint32_t h01, l01, h23, l23;
            split2(v.x, v.y, h01, l01);
            split2(v.z, v.w, h23, l23);
            *(unsigned long long*)(smem + OFF_AH + m_e[it] * 272 + m_kq[it] * 8) =
                ((unsigned long long)h23 << 32) | h01;
            *(unsigned long long*)(smem + OFF_AL + m_e[it] * 272 + m_kq[it] * 8) =
                ((unsigned long long)l23 << 32) | l01;
        }
        #pragma unroll
        for (int half = 0; half < 2; half++) {
            int k = (rb_kp + half * 4) * 2;
            uint32_t hp, lp;
            split2(prb[half].x, prb[half].y, hp, lp);
            *(uint32_t*)(smem + OFF_RBH + rb_e * 48 + k * 2) = hp;
            *(uint32_t*)(smem + OFF_RBL + rb_e * 48 + k * 2) = lp;
        }
        __syncthreads();

        // issue next tile's gmem loads; latency drains behind MMA phase
        int tnext = tile + gridDim.x;
        if (tnext < ntiles) {
            int e0n = tnext << 6;
            #pragma unroll
            for (int it = 0; it < 8; it++) {
                pm[it] = make_float4(0.f, 0.f, 0.f, 0.f);
                if (e0n + m_e[it] < E)
                    pm[it] = *(const float4*)(m + (size_t)(e0n + m_e[it]) * 128 + m_kq[it] * 4);
            }
            #pragma unroll
            for (int half = 0; half < 2; half++) {
                int k = (rb_kp + half * 4) * 2;
                prb[half] = make_float2(0.f, 0.f);
                if (e0n + rb_e < E)
                    prb[half] = *(const float2*)(rbf + (size_t)(e0n + rb_e) * 16 + k);
            }
        }

        float rw[8][4];
        #pragma unroll
        for (int t = 0; t < 8; t++) {
            rw[t][0] = 0.f; rw[t][1] = 0.f; rw[t][2] = 0.f; rw[t][3] = 0.f;
        }
        {
            uint32_t ra0, ra1, ra2, ra3, rl0, rl1, rl2, rl3;
            LDSM4(ra0, ra1, ra2, ra3, rH);
            LDSM4(rl0, rl1, rl2, rl3, rL);
            #pragma unroll
            for (int p = 0; p < 4; p++) {
                uint32_t b0, b1, b2, b3, c0, c1, c2, c3;
                LDSM4T(b0, b1, b2, b3, wrH + p * 32);
                LDSM4T(c0, c1, c2, c3, wrL + p * 32);
                mma_bf16(rw[p * 2], ra0, ra1, ra2, ra3, b0, b1);
                mma_bf16(rw[p * 2], rl0, rl1, rl2, rl3, b0, b1);
                mma_bf16(rw[p * 2], ra0, ra1, ra2, ra3, c0, c1);
                mma_bf16(rw[p * 2 + 1], ra0, ra1, ra2, ra3, b2, b3);
                mma_bf16(rw[p * 2 + 1], rl0, rl1, rl2, rl3, b2, b3);
                mma_bf16(rw[p * 2 + 1], ra0, ra1, ra2, ra3, c2, c3);
            }
        }

        float acc[8][4];
        #pragma unroll
        for (int t = 0; t < 8; t++) {
            acc[t][0] = 0.f; acc[t][1] = 0.f; acc[t][2] = 0.f; acc[t][3] = 0.f;
        }
        #pragma unroll
        for (int ks = 0; ks < 8; ks++) {
            uint32_t ah0, ah1, ah2, ah3, al0, al1, al2, al3;
            LDSM4(ah0, ah1, ah2, ah3, aH + ks * 32);
            LDSM4(al0, al1, al2, al3, aL + ks * 32);
            uint32_t bkb = bH + ks * 16 * 272;
            uint32_t lkb = bL + ks * 16 * 272;
            #pragma unroll
            for (int p = 0; p < 4; p++) {
                uint32_t b0, b1, b2, b3, c0, c1, c2, c3;
                LDSM4T(b0, b1, b2, b3, bkb + p * 32);
                LDSM4T(c0, c1, c2, c3, lkb + p * 32);
                mma_bf16(acc[p * 2], ah0, ah1, ah2, ah3, b0, b1);
                mma_bf16(acc[p * 2], al0, al1, al2, al3, b0, b1);
                mma_bf16(acc[p * 2], ah0, ah1, ah2, ah3, c0, c1);
                mma_bf16(acc[p * 2 + 1], ah0, ah1, ah2, ah3, b2, b3);
                mma_bf16(acc[p * 2 + 1], al0, al1, al2, al3, b2, b3);
                mma_bf16(acc[p * 2 + 1], ah0, ah1, ah2, ah3, c2, c3);
            }
        }

        __syncthreads();

        {
            int row0 = rb * 16 + r_;
            #pragma unroll
            for (int t = 0; t < 8; t++) {
                int colb = (ch * 64 + t * 8 + cc2) * 2;
                float x0 = ssilu(acc[t][0]) * rw[t][0];
                float x1 = ssilu(acc[t][1]) * rw[t][1];
                float x2 = ssilu(acc[t][2]) * rw[t][2];
                float x3 = ssilu(acc[t][3]) * rw[t][3];
                uint32_t hp, lp;
                split2(x0, x1, hp, lp);
                *(uint32_t*)(sXH + row0 * 272 + colb) = hp;
                *(uint32_t*)(sXL + row0 * 272 + colb) = lp;
                split2(x2, x3, hp, lp);
                *(uint32_t*)(sXH + (row0 + 8) * 272 + colb) = hp;
                *(uint32_t*)(sXL + (row0 + 8) * 272 + colb) = lp;
            }
        }
        __syncthreads();

        if (w < 4) {
            float d0[4] = {0.f, 0.f, 0.f, 0.f}, d1[4] = {0.f, 0.f, 0.f, 0.f};
            #pragma unroll
            for (int ks = 0; ks < 8; ks++) {
                uint32_t xh0, xh1, xh2, xh3, xl0, xl1, xl2, xl3;
                LDSM4(xh0, xh1, xh2, xh3, aH + ks * 32);
                LDSM4(xl0, xl1, xl2, xl3, aL + ks * 32);
                uint32_t b0, b1, b2, b3, c0, c1, c2, c3;
                LDSM4T(b0, b1, b2, b3, wdH + ks * 512);
                LDSM4T(c0, c1, c2, c3, wdL + ks * 512);
                mma_bf16(d0, xh0, xh1, xh2, xh3, b0, b1);
                mma_bf16(d0, xl0, xl1, xl2, xl3, b0, b1);
                mma_bf16(d0, xh0, xh1, xh2, xh3, c0, c1);
                mma_bf16(d1, xh0, xh1, xh2, xh3, b2, b3);
                mma_bf16(d1, xl0, xl1, xl2, xl3, b2, b3);
                mma_bf16(d1, xh0, xh1, xh2, xh3, c2, c3);
            }
            int e_row = e0 + rb * 16 + r_;
            if (e_row < E) {
                *(float2*)(g_xdown + (size_t)e_row * 16 + cc2) = make_float2(d0[0], d0[1]);
                *(float2*)(g_xdown + (size_t)e_row * 16 + 8 + cc2) = make_float2(d1[0], d1[1]);
            }
            if (e_row + 8 < E) {
                *(float2*)(g_xdown + (size_t)(e_row + 8) * 16 + cc2) = make_float2(d0[2], d0[3]);
                *(float2*)(g_xdown + (size_t)(e_row + 8) * 16 + 8 + cc2) = make_float2(d1[2], d1[3]);
            }
        }
    }
}

// ---------------- K2: triplet stage via HMMA (pipelined gather) -----------
#define T3_CBH 0
#define T3_CBL 4096
#define T3_WCH 8192
#define T3_WCL 8704
#define T3_XD  9216
#define T3_BA  17408
#define T3_CA  17920
#define T3_SMEM 18432

__global__ __launch_bounds__(256) void k_triplet_hmma(
    const float* __restrict__ cbf,
    const int* __restrict__ ba, const int* __restrict__ ca,
    const float* __restrict__ Wcbf, int T)
{
    __shared__ __align__(16) char smem[T3_SMEM];
    uint32_t sb = smem_u32(smem);
    int tid = threadIdx.x;
    int l = tid & 31, w = tid >> 5;
    int t0 = blockIdx.x << 7;

    int* sBa = (int*)(smem + T3_BA);
    int* sCa = (int*)(smem + T3_CA);
    float* sXd = (float*)(smem + T3_XD);

    if (tid < 128) {
        int k = tid >> 3, n = (tid & 7) * 2;
        float v0 = Wcbf[k * 16 + n], v1 = Wcbf[k * 16 + n + 1];
        uint32_t hp, lp;
        split2(v0, v1, hp, lp);
        *(uint32_t*)(smem + T3_WCH + k * 32 + n * 2) = hp;
        *(uint32_t*)(smem + T3_WCL + k * 32 + n * 2) = lp;
    } else {
        int ti = tid - 128;
        int t = t0 + ti;
        bool ok = t < T;
        sBa[ti] = ok ? ba[t] : 0;
        sCa[ti] = ok ? ca[t] : -1;
    }
    __syncthreads();

    int gr = tid >> 1, ghalf = tid & 1;
    int gb = sBa[gr];
    float4 g0 = *(const float4*)(g_xdown + (size_t)gb * 16 + ghalf * 8);
    float4 g1 = *(const float4*)(g_xdown + (size_t)gb * 16 + ghalf * 8 + 4);

    {
        int e = tid >> 1, q = tid & 1;
        int t = t0 + e;
        bool ok = t < T;
        #pragma unroll
        for (int j = 0; j < 2; j++) {
            int qq = q * 2 + j;
            float4 v = make_float4(0.f, 0.f, 0.f, 0.f);
            if (ok) v = *(const float4*)(cbf + (size_t)t * 16 + qq * 4);
            uint32_t h01, l01, h23, l23;
            split2(v.x, v.y, h01, l01);
            split2(v.z, v.w, h23, l23);
            *(unsigned long long*)(smem + T3_CBH + e * 32 + qq * 8) =
                ((unsigned long long)h23 << 32) | h01;
            *(unsigned long long*)(smem + T3_CBL + e * 32 + qq * 8) =
                ((unsigned long long)l23 << 32) | l01;
        }
    }
    *(float4*)&sXd[gr * 16 + ghalf * 8] = g0;
    *(float4*)&sXd[gr * 16 + ghalf * 8 + 4] = g1;
    __syncthreads();

    int rowm = (l < 16) ? l : (l - 16);
    int colo = (l < 16) ? 0 : 8;
    int r_ = l >> 2, cc = (l & 3) * 2;

    uint32_t aH = sb + T3_CBH + (w * 16 + rowm) * 32 + colo * 2;
    uint32_t aL = aH + (T3_CBL - T3_CBH);
    uint32_t bHa = sb + T3_WCH + rowm * 32 + colo * 2;
    uint32_t bLa = bHa + (T3_WCL - T3_WCH);

    uint32_t ah0, ah1, ah2, ah3, al0, al1, al2, al3;
    uint32_t b0, b1, b2, b3, c0, c1, c2, c3;
    LDSM4(ah0, ah1, ah2, ah3, aH);
    LDSM4(al0, al1, al2, al3, aL);
    LDSM4T(b0, b1, b2, b3, bHa);
    LDSM4T(c0, c1, c2, c3, bLa);

    float u[2][4];
    u[0][0]=u[0][1]=u[0][2]=u[0][3]=0.f;
    u[1][0]=u[1][1]=u[1][2]=u[1][3]=0.f;
    mma_bf16(u[0], ah0, ah1, ah2, ah3, b0, b1);
    mma_bf16(u[0], al0, al1, al2, al3, b0, b1);
    mma_bf16(u[0], ah0, ah1, ah2, ah3, c0, c1);
    mma_bf16(u[1], ah0, ah1, ah2, ah3, b2, b3);
    mma_bf16(u[1], al0, al1, al2, al3, b2, b3);
    mma_bf16(u[1], ah0, ah1, ah2, ah3, c2, c3);

    #pragma unroll
    for (int t = 0; t < 2; t++) {
        int col = t * 8 + cc;
        #pragma unroll
        for (int hh = 0; hh < 2; hh++) {
            int row = w * 16 + r_ + 8 * hh;
            int c_ = sCa[row];
            if (c_ < 0) continue;
            float2 xd = *(float2*)&sXd[row * 16 + col];
            float v0 = u[t][2 * hh] * xd.x;
            float v1 = u[t][2 * hh + 1] * xd.y;
            asm volatile("red.global.add.v2.f32 [%0], {%1,%2};"
                         :: "l"(g_xe + (size_t)c_ * 16 + col),
                            "f"(v0), "f"(v1) : "memory");
        }
    }
}

// ---------------- K3: edge up-projection + atom scatter (HMMA, occ4) ------
#define OFF2_UPH 0
#define OFF2_UPL 4352
#define OFF2_RAH 8704
#define OFF2_RAL 13056
#define OFF2_XEH 17408
#define OFF2_XEL 20480
#define OFF2_RBH 23552
#define OFF2_RBL 26624
#define OFF2_IDX 29696
#define K3_SMEM  29952

__global__ __launch_bounds__(256, 4) void k_edge_up_hmma(
    const float* __restrict__ m, const float* __restrict__ rbf,
    const int* __restrict__ idxt,
    const float* __restrict__ Wup, const float* __restrict__ Wra, int E)
{
    __shared__ __align__(16) char smem[K3_SMEM];
    uint32_t sb = smem_u32(smem);
    int tid = threadIdx.x;
    int l = tid & 31, w = tid >> 5;

    for (int i = tid; i < 1024; i += 256) {
        int k = i >> 6, n = (i & 63) * 2;
        float v0 = Wup[(size_t)k * 128 + n], v1 = Wup[(size_t)k * 128 + n + 1];
        uint32_t hp, lp;
        split2(v0, v1, hp, lp);
        *(uint32_t*)(smem + OFF2_UPH + k * 272 + n * 2) = hp;
        *(uint32_t*)(smem + OFF2_UPL + k * 272 + n * 2) = lp;
        v0 = Wra[(size_t)k * 128 + n]; v1 = Wra[(size_t)k * 128 + n + 1];
        split2(v0, v1, hp, lp);
        *(uint32_t*)(smem + OFF2_RAH + k * 272 + n * 2) = hp;
        *(uint32_t*)(smem + OFF2_RAL + k * 272 + n * 2) = lp;
    }

    int rowm = (l < 16) ? l : (l - 16);
    int colo = (l < 16) ? 0 : 8;
    int rb = w & 3, ch = w >> 2;
    int r_ = l >> 2, cc = (l & 3) * 2;

    uint32_t xH = sb + OFF2_XEH + (rb * 16 + rowm) * 48 + colo * 2;
    uint32_t xL = xH + (OFF2_XEL - OFF2_XEH);
    uint32_t rbH = sb + OFF2_RBH + (rb * 16 + rowm) * 48 + colo * 2;
    uint32_t rbL = rbH + (OFF2_RBL - OFF2_RBH);
    uint32_t bUH = sb + OFF2_UPH + rowm * 272 + (ch * 64 + colo) * 2;
    uint32_t bUL = bUH + (OFF2_UPL - OFF2_UPH);
    uint32_t bRH = sb + OFF2_RAH + rowm * 272 + (ch * 64 + colo) * 2;
    uint32_t bRL = bRH + (OFF2_RAL - OFF2_RAH);
    int* sIdx = (int*)(smem + OFF2_IDX);

    int ntiles = (E + 63) >> 6;
    for (int tile = blockIdx.x; tile < ntiles; tile += gridDim.x) {
        int e0 = tile << 6;
        __syncthreads();

        {
            int e = tid >> 2, q = tid & 3;
            float4 vx = make_float4(0.f, 0.f, 0.f, 0.f), vr = vx;
            if (e0 + e < E) {
                vx = *(const float4*)(g_xe + (size_t)(e0 + e) * 16 + q * 4);
                vr = *(const float4*)(rbf + (size_t)(e0 + e) * 16 + q * 4);
            }
            uint32_t h01, l01, h23, l23;
            split2(vx.x, vx.y, h01, l01); split2(vx.z, vx.w, h23, l23);
            *(unsigned long long*)(smem + OFF2_XEH + e * 48 + q * 8) =
                ((unsigned long long)h23 << 32) | h01;
            *(unsigned long long*)(smem + OFF2_XEL + e * 48 + q * 8) =
                ((unsigned long long)l23 << 32) | l01;
            split2(vr.x, vr.y, h01, l01); split2(vr.z, vr.w, h23, l23);
            *(unsigned long long*)(smem + OFF2_RBH + e * 48 + q * 8) =
                ((unsigned long long)h23 << 32) | h01;
            *(unsigned long long*)(smem + OFF2_RBL + e * 48 + q * 8) =
                ((unsigned long long)l23 << 32) | l01;
        }
        if (tid < 64) sIdx[tid] = (e0 + tid < E) ? idxt[e0 + tid] : -1;
        __syncthreads();

        uint32_t xh0, xh1, xh2, xh3, xl0, xl1, xl2, xl3;
        uint32_t rh0, rh1, rh2, rh3, rl0, rl1, rl2, rl3;
        LDSM4(xh0, xh1, xh2, xh3, xH);
        LDSM4(xl0, xl1, xl2, xl3, xL);
        LDSM4(rh0, rh1, rh2, rh3, rbH);
        LDSM4(rl0, rl1, rl2, rl3, rbL);

        #pragma unroll
        for (int p = 0; p < 4; p++) {
            float u[2][4], rr[2][4];
            u[0][0]=u[0][1]=u[0][2]=u[0][3]=0.f;
            u[1][0]=u[1][1]=u[1][2]=u[1][3]=0.f;
            rr[0][0]=rr[0][1]=rr[0][2]=rr[0][3]=0.f;
            rr[1][0]=rr[1][1]=rr[1][2]=rr[1][3]=0.f;
            {
                uint32_t b0, b1, b2, b3, c0, c1, c2, c3;
                LDSM4T(b0, b1, b2, b3, bUH + p * 32);
                LDSM4T(c0, c1, c2, c3, bUL + p * 32);
                mma_bf16(u[0], xh0, xh1, xh2, xh3, b0, b1);
                mma_bf16(u[0], xl0, xl1, xl2, xl3, b0, b1);
                mma_bf16(u[0], xh0, xh1, xh2, xh3, c0, c1);
                mma_bf16(u[1], xh0, xh1, xh2, xh3, b2, b3);
                mma_bf16(u[1], xl0, xl1, xl2, xl3, b2, b3);
                mma_bf16(u[1], xh0, xh1, xh2, xh3, c2, c3);
            }
            {
                uint32_t b0, b1, b2, b3, c0, c1, c2, c3;
                LDSM4T(b0, b1, b2, b3, bRH + p * 32);
                LDSM4T(c0, c1, c2, c3, bRL + p * 32);
                mma_bf16(rr[0], rh0, rh1, rh2, rh3, b0, b1);
                mma_bf16(rr[0], rl0, rl1, rl2, rl3, b0, b1);
                mma_bf16(rr[0], rh0, rh1, rh2, rh3, c0, c1);
                mma_bf16(rr[1], rh0, rh1, rh2, rh3, b2, b3);
                mma_bf16(rr[1], rl0, rl1, rl2, rl3, b2, b3);
                mma_bf16(rr[1], rh0, rh1, rh2, rh3, c2, c3);
            }
            #pragma unroll
            for (int tt = 0; tt < 2; tt++) {
                int col = ch * 64 + (2 * p + tt) * 8 + cc;
                #pragma unroll
                for (int hh = 0; hh < 2; hh++) {
                    int row = rb * 16 + r_ + 8 * hh;
                    int a = sIdx[row];
                    if (a < 0) continue;
                    float2 mm = *(const float2*)(m + (size_t)(e0 + row) * 128 + col);
                    float h0 = (mm.x + ssilu(u[tt][2 * hh])) * rr[tt][2 * hh];
                    float h1 = (mm.y + ssilu(u[tt][2 * hh + 1])) * rr[tt][2 * hh + 1];
                    asm volatile("red.global.add.v2.f32 [%0], {%1,%2};"
                                 :: "l"(g_h + (size_t)a * 128 + col),
                                    "f"(h0), "f"(h1) : "memory");
                }
            }
        }
    }
}

// ---------------- K4: atom output GEMM via HMMA ----------------
#define K4_BH 0
#define K4_BL 34816
#define K4_AH 69632
#define K4_AL 87040
#define K4_SMEM 104448

__global__ __launch_bounds__(256, 1) void k_atom_out_hmma(
    const float* __restrict__ Watom, float* __restrict__ out, int N)
{
    extern __shared__ char smem[];
    uint32_t sb = smem_u32(smem);
    int tid = threadIdx.x;
    int l = tid & 31, w = tid >> 5;

    for (int i = tid; i < 8192; i += 256) {
        int k = i >> 6, n = (i & 63) * 2;
        float v0 = Watom[(size_t)k * 128 + n];
        float v1 = Watom[(size_t)k * 128 + n + 1];
        uint32_t hp, lp;
        split2(v0, v1, hp, lp);
        *(uint32_t*)(smem + K4_BH + k * 272 + n * 2) = hp;
        *(uint32_t*)(smem + K4_BL + k * 272 + n * 2) = lp;
    }

    int rowm = (l < 16) ? l : (l - 16);
    int colo = (l < 16) ? 0 : 8;
    int rb = w & 3, ch = w >> 2;
    int r_ = l >> 2, cc = (l & 3) * 2;

    uint32_t aH = sb + K4_AH + (rb * 16 + rowm) * 272 + colo * 2;
    uint32_t aL = aH + (K4_AL - K4_AH);
    uint32_t bH = sb + K4_BH + rowm * 272 + (ch * 64 + colo) * 2;
    uint32_t bL = bH + (K4_BL - K4_BH);

    int ntiles = (N + 63) >> 6;
    for (int tile = blockIdx.x; tile < ntiles; tile += gridDim.x) {
        int r0 = tile << 6;
        __syncthreads();

        #pragma unroll 4
        for (int it = 0; it < 8; it++) {
            int r = tid + it * 256;
            int e = r >> 5, kq = r & 31;
            float4 v = make_float4(0.f, 0.f, 0.f, 0.f);
            if (r0 + e < N) v = *(const float4*)(g_h + (size_t)(r0 + e) * 128 + kq * 4);
            uint32_t h01, l01, h23, l23;
            split2(v.x, v.y, h01, l01);
            split2(v.z, v.w, h23, l23);
            *(unsigned long long*)(smem + K4_AH + e * 272 + kq * 8) =
                ((unsigned long long)h23 << 32) | h01;
            *(unsigned long long*)(smem + K4_AL + e * 272 + kq * 8) =
                ((unsigned long long)l23 << 32) | l01;
        }
        __syncthreads();

        float acc[8][4];
        #pragma unroll
        for (int t = 0; t < 8; t++) {
            acc[t][0] = 0.f; acc[t][1] = 0.f; acc[t][2] = 0.f; acc[t][3] = 0.f;
        }
        #pragma unroll
        for (int ks = 0; ks < 8; ks++) {
            uint32_t ah0, ah1, ah2, ah3, al0, al1, al2, al3;
            LDSM4(ah0, ah1, ah2, ah3, aH + ks * 32);
            LDSM4(al0, al1, al2, al3, aL + ks * 32);
            uint32_t bkb = bH + ks * 16 * 272;
            uint32_t lkb = bL + ks * 16 * 272;
            #pragma unroll
            for (int p = 0; p < 4; p++) {
                uint32_t b0, b1, b2, b3, c0, c1, c2, c3;
                LDSM4T(b0, b1, b2, b3, bkb + p * 32);
                LDSM4T(c0, c1, c2, c3, lkb + p * 32);
                mma_bf16(acc[p * 2], ah0, ah1, ah2, ah3, b0, b1);
                mma_bf16(acc[p * 2], al0, al1, al2, al3, b0, b1);
                mma_bf16(acc[p * 2], ah0, ah1, ah2, ah3, c0, c1);
                mma_bf16(acc[p * 2 + 1], ah0, ah1, ah2, ah3, b2, b3);
                mma_bf16(acc[p * 2 + 1], al0, al1, al2, al3, b2, b3);
                mma_bf16(acc[p * 2 + 1], ah0, ah1, ah2, ah3, c2, c3);
            }
        }

        {
            int row0 = r0 + rb * 16 + r_;
            #pragma unroll
            for (int t = 0; t < 8; t++) {
                int col = ch * 64 + t * 8 + cc;
                if (row0 < N) {
                    *(float2*)(out + (size_t)row0 * 128 + col) =
                        make_float2(ssilu(acc[t][0]), ssilu(acc[t][1]));
                }
                if (row0 + 8 < N) {
                    *(float2*)(out + (size_t)(row0 + 8) * 128 + col) =
                        make_float2(ssilu(acc[t][2]), ssilu(acc[t][3]));
                }
            }
        }
    }
}

extern "C" void kernel_launch(void* const* d_in, const int* in_sizes, int n_in,
                              void* d_out, int out_size) {
    const float* m     = (const float*)d_in[0];
    const float* rbf   = (const float*)d_in[1];
    const float* cbf   = (const float*)d_in[2];
    const int*   id3ba = (const int*)d_in[3];
    const int*   id3ca = (const int*)d_in[4];
    const int*   idxt  = (const int*)d_in[5];
    const float* Wba   = (const float*)d_in[6];
    const float* Wrbf  = (const float*)d_in[7];
    const float* Wdown = (const float*)d_in[8];
    const float* Wcbf  = (const float*)d_in[9];
    const float* Wup   = (const float*)d_in[10];
    const float* Wra   = (const float*)d_in[11];
    const float* Watom = (const float*)d_in[12];

    int E = in_sizes[0] / 128;
    int T = in_sizes[2] / 16;
    int N = out_size / 128;

    cudaFuncSetAttribute(k_edge_down_hmma,
                         cudaFuncAttributeMaxDynamicSharedMemorySize, K1_SMEM);
    cudaFuncSetAttribute(k_atom_out_hmma,
                         cudaFuncAttributeMaxDynamicSharedMemorySize, K4_SMEM);

    k_edge_down_hmma<<<148, 256, K1_SMEM>>>(m, rbf, Wba, Wrbf, Wdown, E, N);
    k_triplet_hmma<<<(T + 127) / 128, 256>>>(cbf, id3ba, id3ca, Wcbf, T);
    k_edge_up_hmma<<<1184, 256>>>(m, rbf, idxt, Wup, Wra, E);
    k_atom_out_hmma<<<148, 256, K4_SMEM>>>(Watom, (float*)d_out, N);
}

// round 17
// speedup vs baseline: 1.2011x; 1.0199x over previous
#include <cuda_runtime.h>
#include <cstdint>

#define SSCALE 1.6666666666666667f

__device__ __forceinline__ float ssilu(float x) {
    float e = __expf(-x);
    return SSCALE * __fdividef(x, 1.0f + e);
}

// ---- bf16 split + mma helpers ----
__device__ __forceinline__ void split2(float v0, float v1, uint32_t& hi, uint32_t& lo) {
    asm("cvt.rn.bf16x2.f32 %0, %1, %2;" : "=r"(hi) : "f"(v1), "f"(v0));
    float h0 = __uint_as_float(hi << 16);
    float h1 = __uint_as_float(hi & 0xFFFF0000u);
    float r0 = v0 - h0, r1 = v1 - h1;
    asm("cvt.rn.bf16x2.f32 %0, %1, %2;" : "=r"(lo) : "f"(r1), "f"(r0));
}
__device__ __forceinline__ void mma_bf16(float* d, uint32_t a0, uint32_t a1,
                                         uint32_t a2, uint32_t a3,
                                         uint32_t b0, uint32_t b1) {
    asm("mma.sync.aligned.m16n8k16.row.col.f32.bf16.bf16.f32 "
        "{%0,%1,%2,%3}, {%4,%5,%6,%7}, {%8,%9}, {%0,%1,%2,%3};"
        : "+f"(d[0]), "+f"(d[1]), "+f"(d[2]), "+f"(d[3])
        : "r"(a0), "r"(a1), "r"(a2), "r"(a3), "r"(b0), "r"(b1));
}
#define LDSM4(d0, d1, d2, d3, a) asm volatile( \
    "ldmatrix.sync.aligned.m8n8.x4.shared.b16 {%0,%1,%2,%3}, [%4];" \
    : "=r"(d0), "=r"(d1), "=r"(d2), "=r"(d3) : "r"(a))
#define LDSM4T(d0, d1, d2, d3, a) asm volatile( \
    "ldmatrix.sync.aligned.m8n8.x4.trans.shared.b16 {%0,%1,%2,%3}, [%4];" \
    : "=r"(d0), "=r"(d1), "=r"(d2), "=r"(d3) : "r"(a))

__device__ __forceinline__ uint32_t smem_u32(const void* p) {
    uint32_t a;
    asm("{ .reg .u64 t; cvta.to.shared.u64 t, %1; cvt.u32.u64 %0, t; }"
        : "=r"(a) : "l"(p));
    return a;
}

#define E_MAX 700000
#define N_MAX 40000

__device__ __align__(16) float g_xdown[(size_t)E_MAX * 16];
__device__ __align__(16) float g_xe[(size_t)E_MAX * 16];
__device__ __align__(16) float g_h[(size_t)N_MAX * 128];

// ---------------- K1: edge dense + down projection (all HMMA) -------------
// Zeroes g_xe/g_h in prologue; software-pipelines the m/rbf gmem loads.
#define OFF_BH  0
#define OFF_BL  34816
#define OFF_WRH 69632
#define OFF_WRL 73984
#define OFF_WDH 78336
#define OFF_WDL 82432
#define OFF_AH  86528
#define OFF_AL  103936
#define OFF_RBH 121344
#define OFF_RBL 124416
#define K1_SMEM 127488

__global__ __launch_bounds__(256, 1) void k_edge_down_hmma(
    const float* __restrict__ m, const float* __restrict__ rbf,
    const float* __restrict__ Wba, const float* __restrict__ Wrbf,
    const float* __restrict__ Wdown, int E, int N)
{
    extern __shared__ char smem[];
    uint32_t sb = smem_u32(smem);
    int tid = threadIdx.x;
    int l = tid & 31, w = tid >> 5;

    // zero scratch (grid-stride); drains behind conversion work
    {
        int gi = blockIdx.x * 256 + tid;
        int gs = gridDim.x * 256;
        int n_xe4 = (E * 16) >> 2, n_h4 = (N * 128) >> 2;
        float4 z = make_float4(0.f, 0.f, 0.f, 0.f);
        for (int r = gi; r < n_xe4; r += gs) ((float4*)g_xe)[r] = z;
        for (int r = gi; r < n_h4; r += gs) ((float4*)g_h)[r] = z;
    }

    for (int i = tid; i < 8192; i += 256) {
        int k = i >> 6, n = (i & 63) * 2;
        float v0 = Wba[(size_t)k * 128 + n];
        float v1 = Wba[(size_t)k * 128 + n + 1];
        uint32_t hp, lp;
        split2(v0, v1, hp, lp);
        *(uint32_t*)(smem + OFF_BH + k * 272 + n * 2) = hp;
        *(uint32_t*)(smem + OFF_BL + k * 272 + n * 2) = lp;
    }
    for (int i = tid; i < 1024; i += 256) {
        int k = i >> 6, n = (i & 63) * 2;
        float v0 = Wrbf[(size_t)k * 128 + n];
        float v1 = Wrbf[(size_t)k * 128 + n + 1];
        uint32_t hp, lp;
        split2(v0, v1, hp, lp);
        *(uint32_t*)(smem + OFF_WRH + k * 272 + n * 2) = hp;
        *(uint32_t*)(smem + OFF_WRL + k * 272 + n * 2) = lp;
    }
    for (int i = tid; i < 1024; i += 256) {
        int k = i >> 3, n = (i & 7) * 2;
        float v0 = Wdown[(size_t)k * 16 + n];
        float v1 = Wdown[(size_t)k * 16 + n + 1];
        uint32_t hp, lp;
        split2(v0, v1, hp, lp);
        *(uint32_t*)(smem + OFF_WDH + k * 32 + n * 2) = hp;
        *(uint32_t*)(smem + OFF_WDL + k * 32 + n * 2) = lp;
    }

    int rowm = (l < 16) ? l : (l - 16);
    int colo = (l < 16) ? 0 : 8;
    int rb = w & 3, ch = w >> 2;
    int r_ = l >> 2, cc2 = (l & 3) * 2;

    uint32_t aH = sb + OFF_AH + (rb * 16 + rowm) * 272 + colo * 2;
    uint32_t aL = aH + (OFF_AL - OFF_AH);
    uint32_t rH = sb + OFF_RBH + (rb * 16 + rowm) * 48 + colo * 2;
    uint32_t rL = rH + (OFF_RBL - OFF_RBH);
    uint32_t bH = sb + OFF_BH + rowm * 272 + (ch * 64 + colo) * 2;
    uint32_t bL = bH + (OFF_BL - OFF_BH);
    uint32_t wrH = sb + OFF_WRH + rowm * 272 + (ch * 64 + colo) * 2;
    uint32_t wrL = wrH + (OFF_WRL - OFF_WRH);
    uint32_t wdH = sb + OFF_WDH + rowm * 32 + colo * 2;
    uint32_t wdL = wdH + (OFF_WDL - OFF_WDH);

    char* sXH = smem + OFF_AH;
    char* sXL = smem + OFF_AL;

    int m_e[8], m_kq[8];
    #pragma unroll
    for (int it = 0; it < 8; it++) {
        int r = tid + it * 256;
        m_e[it] = r >> 5;
        m_kq[it] = r & 31;
    }
    int rb_e = tid >> 2, rb_kp = tid & 3;

    int ntiles = (E + 63) >> 6;
    float4 pm[8];
    float2 prb[2];

    {
        int e0 = blockIdx.x << 6;
        #pragma unroll
        for (int it = 0; it < 8; it++) {
            pm[it] = make_float4(0.f, 0.f, 0.f, 0.f);
            if (e0 + m_e[it] < E)
                pm[it] = *(const float4*)(m + (size_t)(e0 + m_e[it]) * 128 + m_kq[it] * 4);
        }
        #pragma unroll
        for (int half = 0; half < 2; half++) {
            int k = (rb_kp + half * 4) * 2;
            prb[half] = make_float2(0.f, 0.f);
            if (e0 + rb_e < E)
                prb[half] = *(const float2*)(rbf + (size_t)(e0 + rb_e) * 16 + k);
        }
    }

    for (int tile = blockIdx.x; tile < ntiles; tile += gridDim.x) {
        int e0 = tile << 6;
        __syncthreads();

        #pragma unroll
        for (int it = 0; it < 8; it++) {
            float4 v = pm[it];
            uint32_t h01, l01, h23, l23;
            split2(v.x, v.y, h01, l01);
            split2(v.z, v.w, h23, l23);
            *(unsigned long long*)(smem + OFF_AH + m_e[it] * 272 + m_kq[it] * 8) =
                ((unsigned long long)h23 << 32) | h01;
            *(unsigned long long*)(smem + OFF_AL + m_e[it] * 272 + m_kq[it] * 8) =
                ((unsigned long long)l23 << 32) | l01;
        }
        #pragma unroll
        for (int half = 0; half < 2; half++) {
            int k = (rb_kp + half * 4) * 2;
            uint32_t hp, lp;
            split2(prb[half].x, prb[half].y, hp, lp);
            *(uint32_t*)(smem + OFF_RBH + rb_e * 48 + k * 2) = hp;
            *(uint32_t*)(smem + OFF_RBL + rb_e * 48 + k * 2) = lp;
        }
        __syncthreads();

        int tnext = tile + gridDim.x;
        if (tnext < ntiles) {
            int e0n = tnext << 6;
            #pragma unroll
            for (int it = 0; it < 8; it++) {
                pm[it] = make_float4(0.f, 0.f, 0.f, 0.f);
                if (e0n + m_e[it] < E)
                    pm[it] = *(const float4*)(m + (size_t)(e0n + m_e[it]) * 128 + m_kq[it] * 4);
            }
            #pragma unroll
            for (int half = 0; half < 2; half++) {
                int k = (rb_kp + half * 4) * 2;
                prb[half] = make_float2(0.f, 0.f);
                if (e0n + rb_e < E)
                    prb[half] = *(const float2*)(rbf + (size_t)(e0n + rb_e) * 16 + k);
            }
        }

        float rw[8][4];
        #pragma unroll
        for (int t = 0; t < 8; t++) {
            rw[t][0] = 0.f; rw[t][1] = 0.f; rw[t][2] = 0.f; rw[t][3] = 0.f;
        }
        {
            uint32_t ra0, ra1, ra2, ra3, rl0, rl1, rl2, rl3;
            LDSM4(ra0, ra1, ra2, ra3, rH);
            LDSM4(rl0, rl1, rl2, rl3, rL);
            #pragma unroll
            for (int p = 0; p < 4; p++) {
                uint32_t b0, b1, b2, b3, c0, c1, c2, c3;
                LDSM4T(b0, b1, b2, b3, wrH + p * 32);
                LDSM4T(c0, c1, c2, c3, wrL + p * 32);
                mma_bf16(rw[p * 2], ra0, ra1, ra2, ra3, b0, b1);
                mma_bf16(rw[p * 2], rl0, rl1, rl2, rl3, b0, b1);
                mma_bf16(rw[p * 2], ra0, ra1, ra2, ra3, c0, c1);
                mma_bf16(rw[p * 2 + 1], ra0, ra1, ra2, ra3, b2, b3);
                mma_bf16(rw[p * 2 + 1], rl0, rl1, rl2, rl3, b2, b3);
                mma_bf16(rw[p * 2 + 1], ra0, ra1, ra2, ra3, c2, c3);
            }
        }

        float acc[8][4];
        #pragma unroll
        for (int t = 0; t < 8; t++) {
            acc[t][0] = 0.f; acc[t][1] = 0.f; acc[t][2] = 0.f; acc[t][3] = 0.f;
        }
        #pragma unroll
        for (int ks = 0; ks < 8; ks++) {
            uint32_t ah0, ah1, ah2, ah3, al0, al1, al2, al3;
            LDSM4(ah0, ah1, ah2, ah3, aH + ks * 32);
            LDSM4(al0, al1, al2, al3, aL + ks * 32);
            uint32_t bkb = bH + ks * 16 * 272;
            uint32_t lkb = bL + ks * 16 * 272;
            #pragma unroll
            for (int p = 0; p < 4; p++) {
                uint32_t b0, b1, b2, b3, c0, c1, c2, c3;
                LDSM4T(b0, b1, b2, b3, bkb + p * 32);
                LDSM4T(c0, c1, c2, c3, lkb + p * 32);
                mma_bf16(acc[p * 2], ah0, ah1, ah2, ah3, b0, b1);
                mma_bf16(acc[p * 2], al0, al1, al2, al3, b0, b1);
                mma_bf16(acc[p * 2], ah0, ah1, ah2, ah3, c0, c1);
                mma_bf16(acc[p * 2 + 1], ah0, ah1, ah2, ah3, b2, b3);
                mma_bf16(acc[p * 2 + 1], al0, al1, al2, al3, b2, b3);
                mma_bf16(acc[p * 2 + 1], ah0, ah1, ah2, ah3, c2, c3);
            }
        }

        __syncthreads();

        {
            int row0 = rb * 16 + r_;
            #pragma unroll
            for (int t = 0; t < 8; t++) {
                int colb = (ch * 64 + t * 8 + cc2) * 2;
                float x0 = ssilu(acc[t][0]) * rw[t][0];
                float x1 = ssilu(acc[t][1]) * rw[t][1];
                float x2 = ssilu(acc[t][2]) * rw[t][2];
                float x3 = ssilu(acc[t][3]) * rw[t][3];
                uint32_t hp, lp;
                split2(x0, x1, hp, lp);
                *(uint32_t*)(sXH + row0 * 272 + colb) = hp;
                *(uint32_t*)(sXL + row0 * 272 + colb) = lp;
                split2(x2, x3, hp, lp);
                *(uint32_t*)(sXH + (row0 + 8) * 272 + colb) = hp;
                *(uint32_t*)(sXL + (row0 + 8) * 272 + colb) = lp;
            }
        }
        __syncthreads();

        if (w < 4) {
            float d0[4] = {0.f, 0.f, 0.f, 0.f}, d1[4] = {0.f, 0.f, 0.f, 0.f};
            #pragma unroll
            for (int ks = 0; ks < 8; ks++) {
                uint32_t xh0, xh1, xh2, xh3, xl0, xl1, xl2, xl3;
                LDSM4(xh0, xh1, xh2, xh3, aH + ks * 32);
                LDSM4(xl0, xl1, xl2, xl3, aL + ks * 32);
                uint32_t b0, b1, b2, b3, c0, c1, c2, c3;
                LDSM4T(b0, b1, b2, b3, wdH + ks * 512);
                LDSM4T(c0, c1, c2, c3, wdL + ks * 512);
                mma_bf16(d0, xh0, xh1, xh2, xh3, b0, b1);
                mma_bf16(d0, xl0, xl1, xl2, xl3, b0, b1);
                mma_bf16(d0, xh0, xh1, xh2, xh3, c0, c1);
                mma_bf16(d1, xh0, xh1, xh2, xh3, b2, b3);
                mma_bf16(d1, xl0, xl1, xl2, xl3, b2, b3);
                mma_bf16(d1, xh0, xh1, xh2, xh3, c2, c3);
            }
            int e_row = e0 + rb * 16 + r_;
            if (e_row < E) {
                *(float2*)(g_xdown + (size_t)e_row * 16 + cc2) = make_float2(d0[0], d0[1]);
                *(float2*)(g_xdown + (size_t)e_row * 16 + 8 + cc2) = make_float2(d1[0], d1[1]);
            }
            if (e_row + 8 < E) {
                *(float2*)(g_xdown + (size_t)(e_row + 8) * 16 + cc2) = make_float2(d0[2], d0[3]);
                *(float2*)(g_xdown + (size_t)(e_row + 8) * 16 + 8 + cc2) = make_float2(d1[2], d1[3]);
            }
        }
    }
}

// ---------------- K2: triplet stage via HMMA (pipelined gather) -----------
#define T3_CBH 0
#define T3_CBL 4096
#define T3_WCH 8192
#define T3_WCL 8704
#define T3_XD  9216
#define T3_BA  17408
#define T3_CA  17920
#define T3_SMEM 18432

__global__ __launch_bounds__(256) void k_triplet_hmma(
    const float* __restrict__ cbf,
    const int* __restrict__ ba, const int* __restrict__ ca,
    const float* __restrict__ Wcbf, int T)
{
    __shared__ __align__(16) char smem[T3_SMEM];
    uint32_t sb = smem_u32(smem);
    int tid = threadIdx.x;
    int l = tid & 31, w = tid >> 5;
    int t0 = blockIdx.x << 7;

    int* sBa = (int*)(smem + T3_BA);
    int* sCa = (int*)(smem + T3_CA);
    float* sXd = (float*)(smem + T3_XD);

    if (tid < 128) {
        int k = tid >> 3, n = (tid & 7) * 2;
        float v0 = Wcbf[k * 16 + n], v1 = Wcbf[k * 16 + n + 1];
        uint32_t hp, lp;
        split2(v0, v1, hp, lp);
        *(uint32_t*)(smem + T3_WCH + k * 32 + n * 2) = hp;
        *(uint32_t*)(smem + T3_WCL + k * 32 + n * 2) = lp;
    } else {
        int ti = tid - 128;
        int t = t0 + ti;
        bool ok = t < T;
        sBa[ti] = ok ? ba[t] : 0;
        sCa[ti] = ok ? ca[t] : -1;
    }
    __syncthreads();

    int gr = tid >> 1, ghalf = tid & 1;
    int gb = sBa[gr];
    float4 g0 = *(const float4*)(g_xdown + (size_t)gb * 16 + ghalf * 8);
    float4 g1 = *(const float4*)(g_xdown + (size_t)gb * 16 + ghalf * 8 + 4);

    {
        int e = tid >> 1, q = tid & 1;
        int t = t0 + e;
        bool ok = t < T;
        #pragma unroll
        for (int j = 0; j < 2; j++) {
            int qq = q * 2 + j;
            float4 v = make_float4(0.f, 0.f, 0.f, 0.f);
            if (ok) v = *(const float4*)(cbf + (size_t)t * 16 + qq * 4);
            uint32_t h01, l01, h23, l23;
            split2(v.x, v.y, h01, l01);
            split2(v.z, v.w, h23, l23);
            *(unsigned long long*)(smem + T3_CBH + e * 32 + qq * 8) =
                ((unsigned long long)h23 << 32) | h01;
            *(unsigned long long*)(smem + T3_CBL + e * 32 + qq * 8) =
                ((unsigned long long)l23 << 32) | l01;
        }
    }
    *(float4*)&sXd[gr * 16 + ghalf * 8] = g0;
    *(float4*)&sXd[gr * 16 + ghalf * 8 + 4] = g1;
    __syncthreads();

    int rowm = (l < 16) ? l : (l - 16);
    int colo = (l < 16) ? 0 : 8;
    int r_ = l >> 2, cc = (l & 3) * 2;

    uint32_t aH = sb + T3_CBH + (w * 16 + rowm) * 32 + colo * 2;
    uint32_t aL = aH + (T3_CBL - T3_CBH);
    uint32_t bHa = sb + T3_WCH + rowm * 32 + colo * 2;
    uint32_t bLa = bHa + (T3_WCL - T3_WCH);

    uint32_t ah0, ah1, ah2, ah3, al0, al1, al2, al3;
    uint32_t b0, b1, b2, b3, c0, c1, c2, c3;
    LDSM4(ah0, ah1, ah2, ah3, aH);
    LDSM4(al0, al1, al2, al3, aL);
    LDSM4T(b0, b1, b2, b3, bHa);
    LDSM4T(c0, c1, c2, c3, bLa);

    float u[2][4];
    u[0][0]=u[0][1]=u[0][2]=u[0][3]=0.f;
    u[1][0]=u[1][1]=u[1][2]=u[1][3]=0.f;
    mma_bf16(u[0], ah0, ah1, ah2, ah3, b0, b1);
    mma_bf16(u[0], al0, al1, al2, al3, b0, b1);
    mma_bf16(u[0], ah0, ah1, ah2, ah3, c0, c1);
    mma_bf16(u[1], ah0, ah1, ah2, ah3, b2, b3);
    mma_bf16(u[1], al0, al1, al2, al3, b2, b3);
    mma_bf16(u[1], ah0, ah1, ah2, ah3, c2, c3);

    #pragma unroll
    for (int t = 0; t < 2; t++) {
        int col = t * 8 + cc;
        #pragma unroll
        for (int hh = 0; hh < 2; hh++) {
            int row = w * 16 + r_ + 8 * hh;
            int c_ = sCa[row];
            if (c_ < 0) continue;
            float2 xd = *(float2*)&sXd[row * 16 + col];
            float v0 = u[t][2 * hh] * xd.x;
            float v1 = u[t][2 * hh + 1] * xd.y;
            asm volatile("red.global.add.v2.f32 [%0], {%1,%2};"
                         :: "l"(g_xe + (size_t)c_ * 16 + col),
                            "f"(v0), "f"(v1) : "memory");
        }
    }
}

// ---------------- K3: edge up-projection + atom scatter (HMMA, occ4,
//                      pipelined tile loads) ------------------------------
#define OFF2_UPH 0
#define OFF2_UPL 4352
#define OFF2_RAH 8704
#define OFF2_RAL 13056
#define OFF2_XEH 17408
#define OFF2_XEL 20480
#define OFF2_RBH 23552
#define OFF2_RBL 26624
#define OFF2_IDX 29696
#define K3_SMEM  29952

__global__ __launch_bounds__(256, 4) void k_edge_up_hmma(
    const float* __restrict__ m, const float* __restrict__ rbf,
    const int* __restrict__ idxt,
    const float* __restrict__ Wup, const float* __restrict__ Wra, int E)
{
    __shared__ __align__(16) char smem[K3_SMEM];
    uint32_t sb = smem_u32(smem);
    int tid = threadIdx.x;
    int l = tid & 31, w = tid >> 5;

    for (int i = tid; i < 1024; i += 256) {
        int k = i >> 6, n = (i & 63) * 2;
        float v0 = Wup[(size_t)k * 128 + n], v1 = Wup[(size_t)k * 128 + n + 1];
        uint32_t hp, lp;
        split2(v0, v1, hp, lp);
        *(uint32_t*)(smem + OFF2_UPH + k * 272 + n * 2) = hp;
        *(uint32_t*)(smem + OFF2_UPL + k * 272 + n * 2) = lp;
        v0 = Wra[(size_t)k * 128 + n]; v1 = Wra[(size_t)k * 128 + n + 1];
        split2(v0, v1, hp, lp);
        *(uint32_t*)(smem + OFF2_RAH + k * 272 + n * 2) = hp;
        *(uint32_t*)(smem + OFF2_RAL + k * 272 + n * 2) = lp;
    }

    int rowm = (l < 16) ? l : (l - 16);
    int colo = (l < 16) ? 0 : 8;
    int rb = w & 3, ch = w >> 2;
    int r_ = l >> 2, cc = (l & 3) * 2;

    uint32_t xH = sb + OFF2_XEH + (rb * 16 + rowm) * 48 + colo * 2;
    uint32_t xL = xH + (OFF2_XEL - OFF2_XEH);
    uint32_t rbH = sb + OFF2_RBH + (rb * 16 + rowm) * 48 + colo * 2;
    uint32_t rbL = rbH + (OFF2_RBL - OFF2_RBH);
    uint32_t bUH = sb + OFF2_UPH + rowm * 272 + (ch * 64 + colo) * 2;
    uint32_t bUL = bUH + (OFF2_UPL - OFF2_UPH);
    uint32_t bRH = sb + OFF2_RAH + rowm * 272 + (ch * 64 + colo) * 2;
    uint32_t bRL = bRH + (OFF2_RAL - OFF2_RAH);
    int* sIdx = (int*)(smem + OFF2_IDX);

    int ld_e = tid >> 2, ld_q = tid & 3;
    int ntiles = (E + 63) >> 6;

    // prefetch first tile
    float4 pvx, pvr;
    int pidx;
    {
        int e0 = blockIdx.x << 6;
        pvx = make_float4(0.f, 0.f, 0.f, 0.f);
        pvr = pvx;
        if (e0 + ld_e < E) {
            pvx = *(const float4*)(g_xe + (size_t)(e0 + ld_e) * 16 + ld_q * 4);
            pvr = *(const float4*)(rbf + (size_t)(e0 + ld_e) * 16 + ld_q * 4);
        }
        pidx = (tid < 64 && e0 + tid < E) ? idxt[e0 + tid] : -1;
    }

    for (int tile = blockIdx.x; tile < ntiles; tile += gridDim.x) {
        int e0 = tile << 6;
        __syncthreads();

        {
            uint32_t h01, l01, h23, l23;
            split2(pvx.x, pvx.y, h01, l01); split2(pvx.z, pvx.w, h23, l23);
            *(unsigned long long*)(smem + OFF2_XEH + ld_e * 48 + ld_q * 8) =
                ((unsigned long long)h23 << 32) | h01;
            *(unsigned long long*)(smem + OFF2_XEL + ld_e * 48 + ld_q * 8) =
                ((unsigned long long)l23 << 32) | l01;
            split2(pvr.x, pvr.y, h01, l01); split2(pvr.z, pvr.w, h23, l23);
            *(unsigned long long*)(smem + OFF2_RBH + ld_e * 48 + ld_q * 8) =
                ((unsigned long long)h23 << 32) | h01;
            *(unsigned long long*)(smem + OFF2_RBL + ld_e * 48 + ld_q * 8) =
                ((unsigned long long)l23 << 32) | l01;
        }
        if (tid < 64) sIdx[tid] = pidx;
        __syncthreads();

        // issue next tile's loads; drain behind MMA + epilogue
        int tnext = tile + gridDim.x;
        if (tnext < ntiles) {
            int e0n = tnext << 6;
            pvx = make_float4(0.f, 0.f, 0.f, 0.f);
            pvr = pvx;
            if (e0n + ld_e < E) {
                pvx = *(const float4*)(g_xe + (size_t)(e0n + ld_e) * 16 + ld_q * 4);
                pvr = *(const float4*)(rbf + (size_t)(e0n + ld_e) * 16 + ld_q * 4);
            }
            pidx = (tid < 64 && e0n + tid < E) ? idxt[e0n + tid] : -1;
        }

        uint32_t xh0, xh1, xh2, xh3, xl0, xl1, xl2, xl3;
        uint32_t rh0, rh1, rh2, rh3, rl0, rl1, rl2, rl3;
        LDSM4(xh0, xh1, xh2, xh3, xH);
        LDSM4(xl0, xl1, xl2, xl3, xL);
        LDSM4(rh0, rh1, rh2, rh3, rbH);
        LDSM4(rl0, rl1, rl2, rl3, rbL);

        #pragma unroll
        for (int p = 0; p < 4; p++) {
            float u[2][4], rr[2][4];
            u[0][0]=u[0][1]=u[0][2]=u[0][3]=0.f;
            u[1][0]=u[1][1]=u[1][2]=u[1][3]=0.f;
            rr[0][0]=rr[0][1]=rr[0][2]=rr[0][3]=0.f;
            rr[1][0]=rr[1][1]=rr[1][2]=rr[1][3]=0.f;
            {
                uint32_t b0, b1, b2, b3, c0, c1, c2, c3;
                LDSM4T(b0, b1, b2, b3, bUH + p * 32);
                LDSM4T(c0, c1, c2, c3, bUL + p * 32);
                mma_bf16(u[0], xh0, xh1, xh2, xh3, b0, b1);
                mma_bf16(u[0], xl0, xl1, xl2, xl3, b0, b1);
                mma_bf16(u[0], xh0, xh1, xh2, xh3, c0, c1);
                mma_bf16(u[1], xh0, xh1, xh2, xh3, b2, b3);
                mma_bf16(u[1], xl0, xl1, xl2, xl3, b2, b3);
                mma_bf16(u[1], xh0, xh1, xh2, xh3, c2, c3);
            }
            {
                uint32_t b0, b1, b2, b3, c0, c1, c2, c3;
                LDSM4T(b0, b1, b2, b3, bRH + p * 32);
                LDSM4T(c0, c1, c2, c3, bRL + p * 32);
                mma_bf16(rr[0], rh0, rh1, rh2, rh3, b0, b1);
                mma_bf16(rr[0], rl0, rl1, rl2, rl3, b0, b1);
                mma_bf16(rr[0], rh0, rh1, rh2, rh3, c0, c1);
                mma_bf16(rr[1], rh0, rh1, rh2, rh3, b2, b3);
                mma_bf16(rr[1], rl0, rl1, rl2, rl3, b2, b3);
                mma_bf16(rr[1], rh0, rh1, rh2, rh3, c2, c3);
            }
            #pragma unroll
            for (int tt = 0; tt < 2; tt++) {
                int col = ch * 64 + (2 * p + tt) * 8 + cc;
                #pragma unroll
                for (int hh = 0; hh < 2; hh++) {
                    int row = rb * 16 + r_ + 8 * hh;
                    int a = sIdx[row];
                    if (a < 0) continue;
                    float2 mm = *(const float2*)(m + (size_t)(e0 + row) * 128 + col);
                    float h0 = (mm.x + ssilu(u[tt][2 * hh])) * rr[tt][2 * hh];
                    float h1 = (mm.y + ssilu(u[tt][2 * hh + 1])) * rr[tt][2 * hh + 1];
                    asm volatile("red.global.add.v2.f32 [%0], {%1,%2};"
                                 :: "l"(g_h + (size_t)a * 128 + col),
                                    "f"(h0), "f"(h1) : "memory");
                }
            }
        }
    }
}

// ---------------- K4: atom output GEMM via HMMA (pipelined) ----------------
#define K4_BH 0
#define K4_BL 34816
#define K4_AH 69632
#define K4_AL 87040
#define K4_SMEM 104448

__global__ __launch_bounds__(256, 1) void k_atom_out_hmma(
    const float* __restrict__ Watom, float* __restrict__ out, int N)
{
    extern __shared__ char smem[];
    uint32_t sb = smem_u32(smem);
    int tid = threadIdx.x;
    int l = tid & 31, w = tid >> 5;

    for (int i = tid; i < 8192; i += 256) {
        int k = i >> 6, n = (i & 63) * 2;
        float v0 = Watom[(size_t)k * 128 + n];
        float v1 = Watom[(size_t)k * 128 + n + 1];
        uint32_t hp, lp;
        split2(v0, v1, hp, lp);
        *(uint32_t*)(smem + K4_BH + k * 272 + n * 2) = hp;
        *(uint32_t*)(smem + K4_BL + k * 272 + n * 2) = lp;
    }

    int rowm = (l < 16) ? l : (l - 16);
    int colo = (l < 16) ? 0 : 8;
    int rb = w & 3, ch = w >> 2;
    int r_ = l >> 2, cc = (l & 3) * 2;

    uint32_t aH = sb + K4_AH + (rb * 16 + rowm) * 272 + colo * 2;
    uint32_t aL = aH + (K4_AL - K4_AH);
    uint32_t bH = sb + K4_BH + rowm * 272 + (ch * 64 + colo) * 2;
    uint32_t bL = bH + (K4_BL - K4_BH);

    int m_e[8], m_kq[8];
    #pragma unroll
    for (int it = 0; it < 8; it++) {
        int r = tid + it * 256;
        m_e[it] = r >> 5;
        m_kq[it] = r & 31;
    }

    int ntiles = (N + 63) >> 6;
    float4 ph[8];
    {
        int r0 = blockIdx.x << 6;
        #pragma unroll
        for (int it = 0; it < 8; it++) {
            ph[it] = make_float4(0.f, 0.f, 0.f, 0.f);
            if (r0 + m_e[it] < N)
                ph[it] = *(const float4*)(g_h + (size_t)(r0 + m_e[it]) * 128 + m_kq[it] * 4);
        }
    }

    for (int tile = blockIdx.x; tile < ntiles; tile += gridDim.x) {
        int r0 = tile << 6;
        __syncthreads();

        #pragma unroll
        for (int it = 0; it < 8; it++) {
            float4 v = ph[it];
            uint32_t h01, l01, h23, l23;
            split2(v.x, v.y, h01, l01);
            split2(v.z, v.w, h23, l23);
            *(unsigned long long*)(smem + K4_AH + m_e[it] * 272 + m_kq[it] * 8) =
                ((unsigned long long)h23 << 32) | h01;
            *(unsigned long long*)(smem + K4_AL + m_e[it] * 272 + m_kq[it] * 8) =
                ((unsigned long long)l23 << 32) | l01;
        }
        __syncthreads();

        int tnext = tile + gridDim.x;
        if (tnext < ntiles) {
            int r0n = tnext << 6;
            #pragma unroll
            for (int it = 0; it < 8; it++) {
                ph[it] = make_float4(0.f, 0.f, 0.f, 0.f);
                if (r0n + m_e[it] < N)
                    ph[it] = *(const float4*)(g_h + (size_t)(r0n + m_e[it]) * 128 + m_kq[it] * 4);
            }
        }

        float acc[8][4];
        #pragma unroll
        for (int t = 0; t < 8; t++) {
            acc[t][0] = 0.f; acc[t][1] = 0.f; acc[t][2] = 0.f; acc[t][3] = 0.f;
        }
        #pragma unroll
        for (int ks = 0; ks < 8; ks++) {
            uint32_t ah0, ah1, ah2, ah3, al0, al1, al2, al3;
            LDSM4(ah0, ah1, ah2, ah3, aH + ks * 32);
            LDSM4(al0, al1, al2, al3, aL + ks * 32);
            uint32_t bkb = bH + ks * 16 * 272;
            uint32_t lkb = bL + ks * 16 * 272;
            #pragma unroll
            for (int p = 0; p < 4; p++) {
                uint32_t b0, b1, b2, b3, c0, c1, c2, c3;
                LDSM4T(b0, b1, b2, b3, bkb + p * 32);
                LDSM4T(c0, c1, c2, c3, lkb + p * 32);
                mma_bf16(acc[p * 2], ah0, ah1, ah2, ah3, b0, b1);
                mma_bf16(acc[p * 2], al0, al1, al2, al3, b0, b1);
                mma_bf16(acc[p * 2], ah0, ah1, ah2, ah3, c0, c1);
                mma_bf16(acc[p * 2 + 1], ah0, ah1, ah2, ah3, b2, b3);
                mma_bf16(acc[p * 2 + 1], al0, al1, al2, al3, b2, b3);
                mma_bf16(acc[p * 2 + 1], ah0, ah1, ah2, ah3, c2, c3);
            }
        }

        {
            int row0 = r0 + rb * 16 + r_;
            #pragma unroll
            for (int t = 0; t < 8; t++) {
                int col = ch * 64 + t * 8 + cc;
                if (row0 < N) {
                    *(float2*)(out + (size_t)row0 * 128 + col) =
                        make_float2(ssilu(acc[t][0]), ssilu(acc[t][1]));
                }
                if (row0 + 8 < N) {
                    *(float2*)(out + (size_t)(row0 + 8) * 128 + col) =
                        make_float2(ssilu(acc[t][2]), ssilu(acc[t][3]));
                }
            }
        }
    }
}

extern "C" void kernel_launch(void* const* d_in, const int* in_sizes, int n_in,
                              void* d_out, int out_size) {
    const float* m     = (const float*)d_in[0];
    const float* rbf   = (const float*)d_in[1];
    const float* cbf   = (const float*)d_in[2];
    const int*   id3ba = (const int*)d_in[3];
    const int*   id3ca = (const int*)d_in[4];
    const int*   idxt  = (const int*)d_in[5];
    const float* Wba   = (const float*)d_in[6];
    const float* Wrbf  = (const float*)d_in[7];
    const float* Wdown = (const float*)d_in[8];
    const float* Wcbf  = (const float*)d_in[9];
    const float* Wup   = (const float*)d_in[10];
    const float* Wra   = (const float*)d_in[11];
    const float* Watom = (const float*)d_in[12];

    int E = in_sizes[0] / 128;
    int T = in_sizes[2] / 16;
    int N = out_size / 128;

    cudaFuncSetAttribute(k_edge_down_hmma,
                         cudaFuncAttributeMaxDynamicSharedMemorySize, K1_SMEM);
    cudaFuncSetAttribute(k_atom_out_hmma,
                         cudaFuncAttributeMaxDynamicSharedMemorySize, K4_SMEM);

    k_edge_down_hmma<<<148, 256, K1_SMEM>>>(m, rbf, Wba, Wrbf, Wdown, E, N);
    k_triplet_hmma<<<(T + 127) / 128, 256>>>(cbf, id3ba, id3ca, Wcbf, T);
    k_edge_up_hmma<<<1184, 256>>>(m, rbf, idxt, Wup, Wra, E);
    k_atom_out_hmma<<<148, 256, K4_SMEM>>>(Watom, (float*)d_out, N);
}